// round 1
// baseline (speedup 1.0000x reference)
#include <cuda_runtime.h>
#include <math.h>

#define S_DIM 2048
#define B_DIM 4
#define H_DIM 1024
#define NHEAD 16
#define DHEAD 64
#define M_DIM (S_DIM * B_DIM)   // 8192 rows for the QKV GEMMs

// Scratch for projected q, k, v: [M, H] each (layout: row m = s*B + b, col = h*64 + d)
__device__ float g_q[(size_t)M_DIM * H_DIM];
__device__ float g_k[(size_t)M_DIM * H_DIM];
__device__ float g_v[(size_t)M_DIM * H_DIM];

// ---------------------------------------------------------------------------
// QKV projection: out[m][n] = sum_k X[m][k] * W[n][k] + bias[n]
// (torch Linear: X @ W^T + b). M=8192, N=K=1024.
// 64x64 block tile, BK=16, 256 threads, 4x4 microtile per thread.
// ---------------------------------------------------------------------------
__global__ __launch_bounds__(256) void qkv_gemm(const float* __restrict__ X,
                                                const float* __restrict__ W,
                                                const float* __restrict__ bias,
                                                int which)
{
    float* out = (which == 0) ? g_q : (which == 1) ? g_k : g_v;

    __shared__ float Xs[16][68];   // Xs[k][m]  (transposed tile, pad 4)
    __shared__ float Ws[16][68];   // Ws[k][n]

    const int tid = threadIdx.x;
    const int tx  = tid & 15;      // -> n microtile
    const int ty  = tid >> 4;      // -> m microtile
    const int m0  = blockIdx.y * 64;
    const int n0  = blockIdx.x * 64;

    const int lrow = tid >> 2;         // 0..63 : row within tile
    const int lcol = (tid & 3) << 2;   // 0,4,8,12 : k offset (float4)

    const float* xp = X + (size_t)(m0 + lrow) * H_DIM + lcol;
    const float* wp = W + (size_t)(n0 + lrow) * H_DIM + lcol;

    float acc[4][4];
#pragma unroll
    for (int i = 0; i < 4; i++)
#pragma unroll
        for (int j = 0; j < 4; j++) acc[i][j] = 0.f;

    for (int k0 = 0; k0 < H_DIM; k0 += 16) {
        float4 xv = *(const float4*)(xp + k0);
        float4 wv = *(const float4*)(wp + k0);
        __syncthreads();   // previous iteration's smem reads done
        Xs[lcol + 0][lrow] = xv.x; Xs[lcol + 1][lrow] = xv.y;
        Xs[lcol + 2][lrow] = xv.z; Xs[lcol + 3][lrow] = xv.w;
        Ws[lcol + 0][lrow] = wv.x; Ws[lcol + 1][lrow] = wv.y;
        Ws[lcol + 2][lrow] = wv.z; Ws[lcol + 3][lrow] = wv.w;
        __syncthreads();
#pragma unroll
        for (int k = 0; k < 16; k++) {
            float4 a4 = *(const float4*)&Xs[k][ty << 2];
            float4 b4 = *(const float4*)&Ws[k][tx << 2];
            float a[4] = {a4.x, a4.y, a4.z, a4.w};
            float b[4] = {b4.x, b4.y, b4.z, b4.w};
#pragma unroll
            for (int i = 0; i < 4; i++)
#pragma unroll
                for (int j = 0; j < 4; j++) acc[i][j] += a[i] * b[j];
        }
    }

    float4 bv = *(const float4*)(bias + n0 + (tx << 2));
    float bb[4] = {bv.x, bv.y, bv.z, bv.w};
#pragma unroll
    for (int i = 0; i < 4; i++) {
        float4 o;
        o.x = acc[i][0] + bb[0];
        o.y = acc[i][1] + bb[1];
        o.z = acc[i][2] + bb[2];
        o.w = acc[i][3] + bb[3];
        *(float4*)(out + (size_t)(m0 + ty * 4 + i) * H_DIM + n0 + (tx << 2)) = o;
    }
}

// ---------------------------------------------------------------------------
// Flash attention, fp32. One CTA = one (head, 64-query tile).
// grid = (S/64, B*NH) = (32, 64). 256 threads, 4x4 microtiles.
// Dynamic smem:
//   Qt[64][68]  : Q^T  (Qt[d][q]), pre-scaled by 1/sqrt(DH)
//   Kt[64][68]  : K^T  (Kt[d][k]); reused as P[t][q] after scores computed
//   Vs[64][68]  : V    (Vs[t][d])
//   m_i[64], l_i[64], alpha[64], maskv[64]
// ---------------------------------------------------------------------------
__global__ __launch_bounds__(256) void attn_kernel(const float* __restrict__ mask,
                                                   float* __restrict__ out)
{
    extern __shared__ float sm[];
    float* Qt    = sm;                 // 64*68
    float* Kt    = Qt + 64 * 68;       // 64*68  (scores/P reuse)
    float* Vs    = Kt + 64 * 68;       // 64*68
    float* m_i   = Vs + 64 * 68;       // 64
    float* l_i   = m_i + 64;           // 64
    float* alpha = l_i + 64;           // 64
    float* maskv = alpha + 64;         // 64

    const int tid  = threadIdx.x;
    const int tx   = tid & 15;         // -> dim / key microtile
    const int ty   = tid >> 4;         // -> query microtile
    const int head = blockIdx.y;       // b*NH + h
    const int b    = head >> 4;
    const int h    = head & 15;
    const int s0   = blockIdx.x * 64;

    const size_t rowstride = (size_t)B_DIM * H_DIM;   // 4096
    const size_t base      = (size_t)b * H_DIM + h * DHEAD;

    const int lrow = tid >> 2;         // 0..63: tile row
    const int dseg = (tid & 3) * 16;   // 0,16,32,48: dim segment (4 float4 each)

    const float SCALE = 0.125f;        // 1/sqrt(64)

    // Load Q tile (transposed, pre-scaled)
    {
        const float* qp = g_q + base + (size_t)(s0 + lrow) * rowstride + dseg;
#pragma unroll
        for (int u = 0; u < 4; u++) {
            float4 v4 = *(const float4*)(qp + 4 * u);
            int d = dseg + 4 * u;
            Qt[(d + 0) * 68 + lrow] = v4.x * SCALE;
            Qt[(d + 1) * 68 + lrow] = v4.y * SCALE;
            Qt[(d + 2) * 68 + lrow] = v4.z * SCALE;
            Qt[(d + 3) * 68 + lrow] = v4.w * SCALE;
        }
    }
    if (tid < 64) { m_i[tid] = -INFINITY; l_i[tid] = 0.f; }

    float o[4][4];
#pragma unroll
    for (int i = 0; i < 4; i++)
#pragma unroll
        for (int j = 0; j < 4; j++) o[i][j] = 0.f;

    for (int t0 = 0; t0 < S_DIM; t0 += 64) {
        // Load K (transposed) and V (natural), plus mask slice
        {
            const float* kp = g_k + base + (size_t)(t0 + lrow) * rowstride + dseg;
            const float* vp = g_v + base + (size_t)(t0 + lrow) * rowstride + dseg;
#pragma unroll
            for (int u = 0; u < 4; u++) {
                float4 kv = *(const float4*)(kp + 4 * u);
                int d = dseg + 4 * u;
                Kt[(d + 0) * 68 + lrow] = kv.x;
                Kt[(d + 1) * 68 + lrow] = kv.y;
                Kt[(d + 2) * 68 + lrow] = kv.z;
                Kt[(d + 3) * 68 + lrow] = kv.w;
                float4 vv = *(const float4*)(vp + 4 * u);
                *(float4*)&Vs[lrow * 68 + d] = vv;
            }
            if (tid < 64) maskv[tid] = mask[(size_t)b * S_DIM + t0 + tid];
        }
        __syncthreads();

        // Scores microtile: sc[i][j] = sum_d Qt[d][ty*4+i] * Kt[d][tx*4+j]
        float sc[4][4];
#pragma unroll
        for (int i = 0; i < 4; i++)
#pragma unroll
            for (int j = 0; j < 4; j++) sc[i][j] = 0.f;
#pragma unroll
        for (int d = 0; d < 64; d++) {
            float4 a4 = *(const float4*)&Qt[d * 68 + (ty << 2)];
            float4 b4 = *(const float4*)&Kt[d * 68 + (tx << 2)];
            float a[4] = {a4.x, a4.y, a4.z, a4.w};
            float bb[4] = {b4.x, b4.y, b4.z, b4.w};
#pragma unroll
            for (int i = 0; i < 4; i++)
#pragma unroll
                for (int j = 0; j < 4; j++) sc[i][j] += a[i] * bb[j];
        }
        __syncthreads();   // done reading Kt; safe to overwrite with P

        // P[t][q] = score + mask[t]   (reuse Kt buffer)
#pragma unroll
        for (int j = 0; j < 4; j++) {
            int t = (tx << 2) + j;
            float mv = maskv[t];
#pragma unroll
            for (int i = 0; i < 4; i++)
                Kt[t * 68 + (ty << 2) + i] = sc[i][j] + mv;
        }
        __syncthreads();

        // Online softmax stats: 4 threads per query row
        {
            const int r = tid >> 2;   // query row
            const int p = tid & 3;    // key-segment
            float lm = -INFINITY;
#pragma unroll
            for (int t = 0; t < 16; t++)
                lm = fmaxf(lm, Kt[(p * 16 + t) * 68 + r]);
            lm = fmaxf(lm, __shfl_xor_sync(0xffffffffu, lm, 1));
            lm = fmaxf(lm, __shfl_xor_sync(0xffffffffu, lm, 2));
            float mold = m_i[r];
            float mnew = fmaxf(mold, lm);
            float ls = 0.f;
#pragma unroll
            for (int t = 0; t < 16; t++) {
                int idx = (p * 16 + t) * 68 + r;
                float e = __expf(Kt[idx] - mnew);
                Kt[idx] = e;
                ls += e;
            }
            ls += __shfl_xor_sync(0xffffffffu, ls, 1);
            ls += __shfl_xor_sync(0xffffffffu, ls, 2);
            if (p == 0) {
                float al = __expf(mold - mnew);
                alpha[r] = al;
                m_i[r]   = mnew;
                l_i[r]   = l_i[r] * al + ls;
            }
        }
        __syncthreads();

        // Rescale existing accumulators
        float al[4];
#pragma unroll
        for (int i = 0; i < 4; i++) al[i] = alpha[(ty << 2) + i];
#pragma unroll
        for (int i = 0; i < 4; i++)
#pragma unroll
            for (int j = 0; j < 4; j++) o[i][j] *= al[i];

        // O += P * V : o[i][j] += sum_t P[t][ty*4+i] * V[t][tx*4+j]
#pragma unroll
        for (int t = 0; t < 64; t++) {
            float4 p4 = *(const float4*)&Kt[t * 68 + (ty << 2)];
            float4 v4 = *(const float4*)&Vs[t * 68 + (tx << 2)];
            float pp[4] = {p4.x, p4.y, p4.z, p4.w};
            float vv[4] = {v4.x, v4.y, v4.z, v4.w};
#pragma unroll
            for (int i = 0; i < 4; i++)
#pragma unroll
                for (int j = 0; j < 4; j++) o[i][j] += pp[i] * vv[j];
        }
        __syncthreads();   // before next tile overwrites Kt/Vs/maskv
    }

    // Epilogue: normalize and store ctx[s, b, h*64+d]
#pragma unroll
    for (int i = 0; i < 4; i++) {
        int q = (ty << 2) + i;
        float inv = 1.f / l_i[q];
        float4 ov;
        ov.x = o[i][0] * inv;
        ov.y = o[i][1] * inv;
        ov.z = o[i][2] * inv;
        ov.w = o[i][3] * inv;
        *(float4*)(out + (size_t)(s0 + q) * rowstride + base + (tx << 2)) = ov;
    }
}

// ---------------------------------------------------------------------------
// Launch
// ---------------------------------------------------------------------------
extern "C" void kernel_launch(void* const* d_in, const int* in_sizes, int n_in,
                              void* d_out, int out_size)
{
    const float* X    = (const float*)d_in[0];   // hidden_states [S,B,H]
    const float* mask = (const float*)d_in[1];   // attention_mask [B,1,1,S]
    const float* Wq   = (const float*)d_in[2];
    const float* bq   = (const float*)d_in[3];
    const float* Wk   = (const float*)d_in[4];
    const float* bk   = (const float*)d_in[5];
    const float* Wv   = (const float*)d_in[6];
    const float* bv   = (const float*)d_in[7];
    float* out = (float*)d_out;

    dim3 ggrid(H_DIM / 64, M_DIM / 64);   // (16, 128)
    qkv_gemm<<<ggrid, 256>>>(X, Wq, bq, 0);
    qkv_gemm<<<ggrid, 256>>>(X, Wk, bk, 1);
    qkv_gemm<<<ggrid, 256>>>(X, Wv, bv, 2);

    const int smem_bytes = (3 * 64 * 68 + 4 * 64) * (int)sizeof(float);  // 53248
    cudaFuncSetAttribute(attn_kernel, cudaFuncAttributeMaxDynamicSharedMemorySize,
                         smem_bytes);
    dim3 agrid(S_DIM / 64, B_DIM * NHEAD);   // (32, 64)
    attn_kernel<<<agrid, 256, smem_bytes>>>(mask, out);
}

// round 2
// speedup vs baseline: 1.9373x; 1.9373x over previous
#include <cuda_runtime.h>
#include <math.h>
#include <stdint.h>

#define S_DIM 2048
#define B_DIM 4
#define H_DIM 1024
#define NHEAD 16
#define DHEAD 64
#define M_DIM (S_DIM * B_DIM)   // 8192

// Scratch for projected q, k, v: [M, H] (row m = s*B + b, col = h*64 + d)
__device__ float g_q[(size_t)M_DIM * H_DIM];
__device__ float g_k[(size_t)M_DIM * H_DIM];
__device__ float g_v[(size_t)M_DIM * H_DIM];

// ---------------------------------------------------------------------------
// helpers: tf32 convert + m16n8k8 tf32 mma
// ---------------------------------------------------------------------------
__device__ __forceinline__ uint32_t f2tf(float x) {
    uint32_t u;
    asm("cvt.rna.tf32.f32 %0, %1;" : "=r"(u) : "f"(x));
    return u;
}

__device__ __forceinline__ void mma8(float c[4],
                                     uint32_t a0, uint32_t a1, uint32_t a2, uint32_t a3,
                                     uint32_t b0, uint32_t b1) {
    asm("mma.sync.aligned.m16n8k8.row.col.f32.tf32.tf32.f32 "
        "{%0,%1,%2,%3},{%4,%5,%6,%7},{%8,%9},{%0,%1,%2,%3};"
        : "+f"(c[0]), "+f"(c[1]), "+f"(c[2]), "+f"(c[3])
        : "r"(a0), "r"(a1), "r"(a2), "r"(a3), "r"(b0), "r"(b1));
}

// ---------------------------------------------------------------------------
// QKV GEMM: out[m][n] = sum_k X[m][k]*W[n][k] + bias[n]   (3-pass tf32 = fp32)
// CTA 128x128, BK=32, 256 threads. Warp grid 4(M)x2(N): warp tile 32x64.
// Per warp: 2 m-tiles x 8 n-tiles of m16n8k8.
// ---------------------------------------------------------------------------
__global__ __launch_bounds__(256, 1) void qkv_gemm_tc(const float* __restrict__ X,
                                                      const float* __restrict__ W,
                                                      const float* __restrict__ bias,
                                                      int which)
{
    float* out = (which == 0) ? g_q : (which == 1) ? g_k : g_v;

    __shared__ float Xs[128 * 36];   // [row][k], stride 36 (conflict-free frags)
    __shared__ float Ws[128 * 36];   // [n][k]

    const int tid  = threadIdx.x;
    const int lane = tid & 31, warp = tid >> 5;
    const int g = lane >> 2, t = lane & 3;
    const int wm = warp & 3, wn = warp >> 2;
    const int m0 = blockIdx.y * 128, n0 = blockIdx.x * 128;

    const int lr = tid >> 1;          // 0..127
    const int lc = (tid & 1) * 16;    // 0 or 16

    const float* xp = X + (size_t)(m0 + lr) * H_DIM + lc;
    const float* wp = W + (size_t)(n0 + lr) * H_DIM + lc;

    float acc[2][8][4];
#pragma unroll
    for (int i = 0; i < 2; i++)
#pragma unroll
        for (int j = 0; j < 8; j++)
#pragma unroll
            for (int r = 0; r < 4; r++) acc[i][j][r] = 0.f;

    float4 xv[4], wv[4];
#pragma unroll
    for (int u = 0; u < 4; u++) {
        xv[u] = *(const float4*)(xp + 4 * u);
        wv[u] = *(const float4*)(wp + 4 * u);
    }

    for (int k0 = 0; k0 < H_DIM; k0 += 32) {
        __syncthreads();
#pragma unroll
        for (int u = 0; u < 4; u++) {
            *(float4*)&Xs[lr * 36 + lc + 4 * u] = xv[u];
            *(float4*)&Ws[lr * 36 + lc + 4 * u] = wv[u];
        }
        __syncthreads();
        if (k0 + 32 < H_DIM) {
#pragma unroll
            for (int u = 0; u < 4; u++) {
                xv[u] = *(const float4*)(xp + k0 + 32 + 4 * u);
                wv[u] = *(const float4*)(wp + k0 + 32 + 4 * u);
            }
        }

#pragma unroll
        for (int ks = 0; ks < 4; ks++) {
            uint32_t ah[2][4], al[2][4];
#pragma unroll
            for (int mt = 0; mt < 2; mt++) {
                const int row = wm * 32 + mt * 16;
                float a0 = Xs[(row + g)     * 36 + ks * 8 + t];
                float a1 = Xs[(row + g + 8) * 36 + ks * 8 + t];
                float a2 = Xs[(row + g)     * 36 + ks * 8 + t + 4];
                float a3 = Xs[(row + g + 8) * 36 + ks * 8 + t + 4];
                ah[mt][0] = f2tf(a0); al[mt][0] = f2tf(a0 - __uint_as_float(ah[mt][0]));
                ah[mt][1] = f2tf(a1); al[mt][1] = f2tf(a1 - __uint_as_float(ah[mt][1]));
                ah[mt][2] = f2tf(a2); al[mt][2] = f2tf(a2 - __uint_as_float(ah[mt][2]));
                ah[mt][3] = f2tf(a3); al[mt][3] = f2tf(a3 - __uint_as_float(ah[mt][3]));
            }
#pragma unroll
            for (int nt = 0; nt < 8; nt++) {
                const int nr = wn * 64 + nt * 8 + g;
                float b0f = Ws[nr * 36 + ks * 8 + t];
                float b1f = Ws[nr * 36 + ks * 8 + t + 4];
                uint32_t bh0 = f2tf(b0f), bl0 = f2tf(b0f - __uint_as_float(bh0));
                uint32_t bh1 = f2tf(b1f), bl1 = f2tf(b1f - __uint_as_float(bh1));
#pragma unroll
                for (int mt = 0; mt < 2; mt++) {
                    mma8(acc[mt][nt], ah[mt][0], ah[mt][1], ah[mt][2], ah[mt][3], bh0, bh1);
                    mma8(acc[mt][nt], ah[mt][0], ah[mt][1], ah[mt][2], ah[mt][3], bl0, bl1);
                    mma8(acc[mt][nt], al[mt][0], al[mt][1], al[mt][2], al[mt][3], bh0, bh1);
                }
            }
        }
    }

    // epilogue
#pragma unroll
    for (int nt = 0; nt < 8; nt++) {
        const int col = n0 + wn * 64 + nt * 8 + 2 * t;
        const float b0 = bias[col], b1 = bias[col + 1];
#pragma unroll
        for (int mt = 0; mt < 2; mt++) {
            const int r0 = m0 + wm * 32 + mt * 16 + g;
            float2 o0 = make_float2(acc[mt][nt][0] + b0, acc[mt][nt][1] + b1);
            float2 o1 = make_float2(acc[mt][nt][2] + b0, acc[mt][nt][3] + b1);
            *(float2*)(out + (size_t)r0 * H_DIM + col)       = o0;
            *(float2*)(out + (size_t)(r0 + 8) * H_DIM + col) = o1;
        }
    }
}

// ---------------------------------------------------------------------------
// Flash attention with tf32 mma. One CTA = (head, 128-query tile).
// 8 warps x 16 query rows. Key tiles of 64. Online softmax in registers
// (each query row lives inside one lane-quad of the mma accumulator).
// ---------------------------------------------------------------------------
__global__ __launch_bounds__(256, 1) void attn_tc(const float* __restrict__ mask,
                                                  float* __restrict__ out)
{
    extern __shared__ float sm[];
    float* Ks    = sm;                 // [64][68]  (K tile, [t][d])
    float* Vs    = Ks + 64 * 68;       // [64][68]  (V tile, [t][d])
    float* Ps    = Vs + 64 * 68;       // [128][68] (P, [q][t])
    float* maskv = Ps + 128 * 68;      // [64]

    const int tid  = threadIdx.x;
    const int lane = tid & 31, warp = tid >> 5;
    const int g = lane >> 2, t = lane & 3;
    const int head = blockIdx.y, b = head >> 4, h = head & 15;
    const int s0 = blockIdx.x * 128;

    const size_t rs   = (size_t)B_DIM * H_DIM;          // 4096
    const size_t base = (size_t)b * H_DIM + h * DHEAD;

    // Q fragments (hi only), pre-scaled by 1/sqrt(64)
    uint32_t qf[8][4];
    {
        const float* qp = g_q + base + (size_t)(s0 + warp * 16) * rs;
#pragma unroll
        for (int ks = 0; ks < 8; ks++) {
            qf[ks][0] = f2tf(qp[(size_t)g       * rs + ks * 8 + t]     * 0.125f);
            qf[ks][1] = f2tf(qp[(size_t)(g + 8) * rs + ks * 8 + t]     * 0.125f);
            qf[ks][2] = f2tf(qp[(size_t)g       * rs + ks * 8 + t + 4] * 0.125f);
            qf[ks][3] = f2tf(qp[(size_t)(g + 8) * rs + ks * 8 + t + 4] * 0.125f);
        }
    }

    float m0r = -INFINITY, m1r = -INFINITY, l0 = 0.f, l1 = 0.f;
    float oacc[8][4];
#pragma unroll
    for (int j = 0; j < 8; j++)
#pragma unroll
        for (int r = 0; r < 4; r++) oacc[j][r] = 0.f;

    const int lr = tid >> 2;           // 0..63
    const int lc = (tid & 3) * 16;     // 0,16,32,48
    const float* kp = g_k + base + lc;
    const float* vp = g_v + base + lc;
    const int prow = warp * 16 + g;

    for (int t0 = 0; t0 < S_DIM; t0 += 64) {
#pragma unroll
        for (int u = 0; u < 4; u++) {
            *(float4*)&Ks[lr * 68 + lc + 4 * u] =
                *(const float4*)(kp + (size_t)(t0 + lr) * rs + 4 * u);
            *(float4*)&Vs[lr * 68 + lc + 4 * u] =
                *(const float4*)(vp + (size_t)(t0 + lr) * rs + 4 * u);
        }
        if (tid < 64) maskv[tid] = mask[(size_t)b * S_DIM + t0 + tid];
        __syncthreads();

        // scores: S = Q K^T  (16q x 64t per warp)
        float sacc[8][4];
#pragma unroll
        for (int j = 0; j < 8; j++)
#pragma unroll
            for (int r = 0; r < 4; r++) sacc[j][r] = 0.f;
#pragma unroll
        for (int ks = 0; ks < 8; ks++) {
#pragma unroll
            for (int nt = 0; nt < 8; nt++) {
                const int kr = nt * 8 + g;
                uint32_t b0 = f2tf(Ks[kr * 68 + ks * 8 + t]);
                uint32_t b1 = f2tf(Ks[kr * 68 + ks * 8 + t + 4]);
                mma8(sacc[nt], qf[ks][0], qf[ks][1], qf[ks][2], qf[ks][3], b0, b1);
            }
        }

        // + mask, row max
        float tm0 = -INFINITY, tm1 = -INFINITY;
#pragma unroll
        for (int nt = 0; nt < 8; nt++) {
            const float mv0 = maskv[nt * 8 + 2 * t];
            const float mv1 = maskv[nt * 8 + 2 * t + 1];
            sacc[nt][0] += mv0; sacc[nt][1] += mv1;
            sacc[nt][2] += mv0; sacc[nt][3] += mv1;
            tm0 = fmaxf(tm0, fmaxf(sacc[nt][0], sacc[nt][1]));
            tm1 = fmaxf(tm1, fmaxf(sacc[nt][2], sacc[nt][3]));
        }
        tm0 = fmaxf(tm0, __shfl_xor_sync(0xffffffffu, tm0, 1));
        tm0 = fmaxf(tm0, __shfl_xor_sync(0xffffffffu, tm0, 2));
        tm1 = fmaxf(tm1, __shfl_xor_sync(0xffffffffu, tm1, 1));
        tm1 = fmaxf(tm1, __shfl_xor_sync(0xffffffffu, tm1, 2));

        const float mn0 = fmaxf(m0r, tm0), mn1 = fmaxf(m1r, tm1);
        const float al0 = __expf(m0r - mn0), al1 = __expf(m1r - mn1);
        m0r = mn0; m1r = mn1;

        // P = exp(s - m), store to smem, row sums
        float ls0 = 0.f, ls1 = 0.f;
#pragma unroll
        for (int nt = 0; nt < 8; nt++) {
            float p0 = __expf(sacc[nt][0] - mn0);
            float p1 = __expf(sacc[nt][1] - mn0);
            float p2 = __expf(sacc[nt][2] - mn1);
            float p3 = __expf(sacc[nt][3] - mn1);
            ls0 += p0 + p1; ls1 += p2 + p3;
            *(float2*)&Ps[prow * 68 + nt * 8 + 2 * t]       = make_float2(p0, p1);
            *(float2*)&Ps[(prow + 8) * 68 + nt * 8 + 2 * t] = make_float2(p2, p3);
        }
        ls0 += __shfl_xor_sync(0xffffffffu, ls0, 1);
        ls0 += __shfl_xor_sync(0xffffffffu, ls0, 2);
        ls1 += __shfl_xor_sync(0xffffffffu, ls1, 1);
        ls1 += __shfl_xor_sync(0xffffffffu, ls1, 2);
        l0 = l0 * al0 + ls0;
        l1 = l1 * al1 + ls1;

        // rescale O
#pragma unroll
        for (int nt = 0; nt < 8; nt++) {
            oacc[nt][0] *= al0; oacc[nt][1] *= al0;
            oacc[nt][2] *= al1; oacc[nt][3] *= al1;
        }

        __syncwarp();   // P tile is warp-private (this warp's rows only)

        // O += P V
#pragma unroll
        for (int ks = 0; ks < 8; ks++) {
            uint32_t a0 = f2tf(Ps[prow * 68 + ks * 8 + t]);
            uint32_t a1 = f2tf(Ps[(prow + 8) * 68 + ks * 8 + t]);
            uint32_t a2 = f2tf(Ps[prow * 68 + ks * 8 + t + 4]);
            uint32_t a3 = f2tf(Ps[(prow + 8) * 68 + ks * 8 + t + 4]);
#pragma unroll
            for (int nt = 0; nt < 8; nt++) {
                uint32_t b0 = f2tf(Vs[(ks * 8 + t)     * 68 + nt * 8 + g]);
                uint32_t b1 = f2tf(Vs[(ks * 8 + t + 4) * 68 + nt * 8 + g]);
                mma8(oacc[nt], a0, a1, a2, a3, b0, b1);
            }
        }
        __syncthreads();   // before next tile overwrites Ks/Vs
    }

    // epilogue: normalize + store
    const float inv0 = 1.f / l0, inv1 = 1.f / l1;
    float* op = out + (size_t)(s0 + warp * 16) * rs + base;
#pragma unroll
    for (int nt = 0; nt < 8; nt++) {
        *(float2*)(op + (size_t)g * rs + nt * 8 + 2 * t) =
            make_float2(oacc[nt][0] * inv0, oacc[nt][1] * inv0);
        *(float2*)(op + (size_t)(g + 8) * rs + nt * 8 + 2 * t) =
            make_float2(oacc[nt][2] * inv1, oacc[nt][3] * inv1);
    }
}

// ---------------------------------------------------------------------------
extern "C" void kernel_launch(void* const* d_in, const int* in_sizes, int n_in,
                              void* d_out, int out_size)
{
    const float* X    = (const float*)d_in[0];
    const float* mask = (const float*)d_in[1];
    const float* Wq   = (const float*)d_in[2];
    const float* bq   = (const float*)d_in[3];
    const float* Wk   = (const float*)d_in[4];
    const float* bk   = (const float*)d_in[5];
    const float* Wv   = (const float*)d_in[6];
    const float* bv   = (const float*)d_in[7];
    float* out = (float*)d_out;

    dim3 ggrid(H_DIM / 128, M_DIM / 128);   // (8, 64)
    qkv_gemm_tc<<<ggrid, 256>>>(X, Wq, bq, 0);
    qkv_gemm_tc<<<ggrid, 256>>>(X, Wk, bk, 1);
    qkv_gemm_tc<<<ggrid, 256>>>(X, Wv, bv, 2);

    const int smem_bytes = (64 * 68 * 2 + 128 * 68 + 64) * (int)sizeof(float); // 69888
    cudaFuncSetAttribute(attn_tc, cudaFuncAttributeMaxDynamicSharedMemorySize,
                         smem_bytes);
    dim3 agrid(S_DIM / 128, B_DIM * NHEAD);   // (16, 64)
    attn_tc<<<agrid, 256, smem_bytes>>>(mask, out);
}

// round 4
// speedup vs baseline: 4.0743x; 2.1031x over previous
#include <cuda_runtime.h>
#include <cuda_fp16.h>
#include <math.h>
#include <stdint.h>

#define S_DIM 2048
#define B_DIM 4
#define H_DIM 1024
#define NHEAD 16
#define DHEAD 64
#define M_DIM (S_DIM * B_DIM)   // 8192

// Projected q,k,v in fp16: [M, H] (row m = s*B + b, col = h*64 + d)
__device__ __half g_q[(size_t)M_DIM * H_DIM];
__device__ __half g_k[(size_t)M_DIM * H_DIM];
__device__ __half g_v[(size_t)M_DIM * H_DIM];

// ---------------------------------------------------------------------------
// helpers
// ---------------------------------------------------------------------------
__device__ __forceinline__ uint32_t sma(const void* p) {
    return (uint32_t)__cvta_generic_to_shared(p);
}
__device__ __forceinline__ void ldm4(uint32_t r[4], uint32_t a) {
    asm volatile("ldmatrix.sync.aligned.m8n8.x4.shared.b16 {%0,%1,%2,%3},[%4];"
                 : "=r"(r[0]), "=r"(r[1]), "=r"(r[2]), "=r"(r[3]) : "r"(a));
}
__device__ __forceinline__ void ldm4t(uint32_t r[4], uint32_t a) {
    asm volatile("ldmatrix.sync.aligned.m8n8.x4.trans.shared.b16 {%0,%1,%2,%3},[%4];"
                 : "=r"(r[0]), "=r"(r[1]), "=r"(r[2]), "=r"(r[3]) : "r"(a));
}
__device__ __forceinline__ void mma16(float c[4], const uint32_t a[4],
                                      uint32_t b0, uint32_t b1) {
    asm volatile("mma.sync.aligned.m16n8k16.row.col.f32.f16.f16.f32 "
                 "{%0,%1,%2,%3},{%4,%5,%6,%7},{%8,%9},{%0,%1,%2,%3};"
                 : "+f"(c[0]), "+f"(c[1]), "+f"(c[2]), "+f"(c[3])
                 : "r"(a[0]), "r"(a[1]), "r"(a[2]), "r"(a[3]), "r"(b0), "r"(b1));
}
__device__ __forceinline__ uint32_t h2u(__half2 h) {
    return *reinterpret_cast<uint32_t*>(&h);
}

// ---------------------------------------------------------------------------
// Fused QKV GEMM, fp16 3-pass split (hh+hl+lh ~= fp32 exact).
// out[m][n] = sum_k X[m][k]*W[n][k] + bias[n].  M=8192, N=K=1024.
// CTA 128x128, BK=32, 256 threads. Warp grid 4(M)x2(N), warp tile 32x64.
// blockIdx.z selects Q/K/V.
// ---------------------------------------------------------------------------
__global__ __launch_bounds__(256) void qkv_fp16(
    const float* __restrict__ X,
    const float* __restrict__ Wq, const float* __restrict__ bq,
    const float* __restrict__ Wk, const float* __restrict__ bk,
    const float* __restrict__ Wv, const float* __restrict__ bv)
{
    const int which = blockIdx.z;
    const float* W    = (which == 0) ? Wq : (which == 1) ? Wk : Wv;
    const float* bias = (which == 0) ? bq : (which == 1) ? bk : bv;
    __half* out       = (which == 0) ? g_q : (which == 1) ? g_k : g_v;

    __shared__ __half Xh[128 * 40], Xl[128 * 40];   // stride 40: ldmatrix conflict-free
    __shared__ __half Wh[128 * 40], Wl[128 * 40];

    const int tid  = threadIdx.x;
    const int lane = tid & 31, warp = tid >> 5;
    const int g = lane >> 2, t = lane & 3;
    const int wm = warp & 3, wn = warp >> 2;
    const int m0 = blockIdx.y * 128, n0 = blockIdx.x * 128;

    const int lr = tid >> 1;          // 0..127
    const int lc = (tid & 1) * 16;    // 0 / 16

    const float* xp = X + (size_t)(m0 + lr) * H_DIM + lc;
    const float* wp = W + (size_t)(n0 + lr) * H_DIM + lc;

    float acc[2][8][4];
#pragma unroll
    for (int i = 0; i < 2; i++)
#pragma unroll
        for (int j = 0; j < 8; j++)
#pragma unroll
            for (int r = 0; r < 4; r++) acc[i][j][r] = 0.f;

    // ldmatrix lane base addresses
    const int asel = lane & 15, ablk = (lane >> 4) * 8;           // A pattern
    const int br = lane & 7, bs = lane >> 3;                      // B pattern
    const uint32_t aXh = sma(Xh) + (uint32_t)(((wm * 32 + asel) * 40 + ablk) * 2);
    const uint32_t aXl = sma(Xl) + (uint32_t)(((wm * 32 + asel) * 40 + ablk) * 2);
    const uint32_t bWh = sma(Wh) +
        (uint32_t)(((wn * 64 + br + (bs >> 1) * 8) * 40 + (bs & 1) * 8) * 2);
    const uint32_t bWl = sma(Wl) +
        (uint32_t)(((wn * 64 + br + (bs >> 1) * 8) * 40 + (bs & 1) * 8) * 2);

    float4 xv[4], wv[4];
#pragma unroll
    for (int u = 0; u < 4; u++) {
        xv[u] = *(const float4*)(xp + 4 * u);
        wv[u] = *(const float4*)(wp + 4 * u);
    }

    for (int k0 = 0; k0 < H_DIM; k0 += 32) {
        __syncthreads();
#pragma unroll
        for (int u = 0; u < 4; u++) {
            // split X
            __half hx0 = __float2half_rn(xv[u].x), hx1 = __float2half_rn(xv[u].y);
            __half hx2 = __float2half_rn(xv[u].z), hx3 = __float2half_rn(xv[u].w);
            __half lx0 = __float2half_rn(xv[u].x - __half2float(hx0));
            __half lx1 = __float2half_rn(xv[u].y - __half2float(hx1));
            __half lx2 = __float2half_rn(xv[u].z - __half2float(hx2));
            __half lx3 = __float2half_rn(xv[u].w - __half2float(hx3));
            uint2 ph = make_uint2(h2u(__halves2half2(hx0, hx1)), h2u(__halves2half2(hx2, hx3)));
            uint2 pl = make_uint2(h2u(__halves2half2(lx0, lx1)), h2u(__halves2half2(lx2, lx3)));
            *(uint2*)&Xh[lr * 40 + lc + 4 * u] = ph;
            *(uint2*)&Xl[lr * 40 + lc + 4 * u] = pl;
            // split W
            __half hw0 = __float2half_rn(wv[u].x), hw1 = __float2half_rn(wv[u].y);
            __half hw2 = __float2half_rn(wv[u].z), hw3 = __float2half_rn(wv[u].w);
            __half lw0 = __float2half_rn(wv[u].x - __half2float(hw0));
            __half lw1 = __float2half_rn(wv[u].y - __half2float(hw1));
            __half lw2 = __float2half_rn(wv[u].z - __half2float(hw2));
            __half lw3 = __float2half_rn(wv[u].w - __half2float(hw3));
            uint2 qh = make_uint2(h2u(__halves2half2(hw0, hw1)), h2u(__halves2half2(hw2, hw3)));
            uint2 ql = make_uint2(h2u(__halves2half2(lw0, lw1)), h2u(__halves2half2(lw2, lw3)));
            *(uint2*)&Wh[lr * 40 + lc + 4 * u] = qh;
            *(uint2*)&Wl[lr * 40 + lc + 4 * u] = ql;
        }
        __syncthreads();

        if (k0 + 32 < H_DIM) {
#pragma unroll
            for (int u = 0; u < 4; u++) {
                xv[u] = *(const float4*)(xp + k0 + 32 + 4 * u);
                wv[u] = *(const float4*)(wp + k0 + 32 + 4 * u);
            }
        }

#pragma unroll
        for (int kc = 0; kc < 2; kc++) {
            uint32_t ah[2][4], al[2][4];
#pragma unroll
            for (int mt = 0; mt < 2; mt++) {
                ldm4(ah[mt], aXh + (uint32_t)((mt * 16 * 40 + kc * 16) * 2));
                ldm4(al[mt], aXl + (uint32_t)((mt * 16 * 40 + kc * 16) * 2));
            }
#pragma unroll
            for (int ntp = 0; ntp < 4; ntp++) {
                uint32_t bh[4], bl[4];
                ldm4(bh, bWh + (uint32_t)((ntp * 16 * 40 + kc * 16) * 2));
                ldm4(bl, bWl + (uint32_t)((ntp * 16 * 40 + kc * 16) * 2));
#pragma unroll
                for (int half_n = 0; half_n < 2; half_n++) {
                    const int nt = 2 * ntp + half_n;
                    const uint32_t b0h = bh[2 * half_n], b1h = bh[2 * half_n + 1];
                    const uint32_t b0l = bl[2 * half_n], b1l = bl[2 * half_n + 1];
#pragma unroll
                    for (int mt = 0; mt < 2; mt++) {
                        mma16(acc[mt][nt], ah[mt], b0h, b1h);
                        mma16(acc[mt][nt], ah[mt], b0l, b1l);
                        mma16(acc[mt][nt], al[mt], b0h, b1h);
                    }
                }
            }
        }
    }

    // epilogue: +bias, convert to fp16
#pragma unroll
    for (int nt = 0; nt < 8; nt++) {
        const int col = n0 + wn * 64 + nt * 8 + 2 * t;
        const float b0 = bias[col], b1 = bias[col + 1];
#pragma unroll
        for (int mt = 0; mt < 2; mt++) {
            const int r0 = m0 + wm * 32 + mt * 16 + g;
            *(__half2*)(out + (size_t)r0 * H_DIM + col) =
                __floats2half2_rn(acc[mt][nt][0] + b0, acc[mt][nt][1] + b1);
            *(__half2*)(out + (size_t)(r0 + 8) * H_DIM + col) =
                __floats2half2_rn(acc[mt][nt][2] + b0, acc[mt][nt][3] + b1);
        }
    }
}

// ---------------------------------------------------------------------------
// Flash attention, fp16 mma + ldmatrix. CTA = (head, 128 queries), 8 warps
// x 16 query rows, key tiles of 64. Online softmax in registers.
// ---------------------------------------------------------------------------
__global__ __launch_bounds__(256, 2) void attn_fp16(const float* __restrict__ mask,
                                                    float* __restrict__ out)
{
    __shared__ __half Ks[64 * 72];     // [key][d], stride 72 (conflict-free)
    __shared__ __half Vs[64 * 72];     // [key][d]
    __shared__ __half Ps[128 * 72];    // [q][key]; also Q staging [q][d]
    __shared__ float  maskv[64];

    const int tid  = threadIdx.x;
    const int lane = tid & 31, warp = tid >> 5;
    const int g = lane >> 2, t = lane & 3;
    const int head = blockIdx.y, b = head >> 4, h = head & 15;
    const int s0 = blockIdx.x * 128;

    const size_t rs   = (size_t)B_DIM * H_DIM;          // 4096
    const size_t base = (size_t)b * H_DIM + h * DHEAD;

    // lane base addresses
    const int asel = lane & 15, ablk = (lane >> 4) * 8;
    const int br = lane & 7, bs = lane >> 3;
    const uint32_t aP = sma(Ps) + (uint32_t)(((warp * 16 + asel) * 72 + ablk) * 2);
    const uint32_t bK = sma(Ks) +
        (uint32_t)(((br + (bs >> 1) * 8) * 72 + (bs & 1) * 8) * 2);
    const uint32_t bV = sma(Vs) +
        (uint32_t)(((br + (bs & 1) * 8) * 72 + (bs >> 1) * 8) * 2);

    // ---- stage Q into Ps, build Q fragments (scaled by 1/8, exact) ----
    {
        const int qlr = tid >> 1, qlc = (tid & 1) * 32;
        const __half* qp = g_q + base + (size_t)(s0 + qlr) * rs + qlc;
#pragma unroll
        for (int u = 0; u < 4; u++)
            *(uint4*)&Ps[qlr * 72 + qlc + 8 * u] = *(const uint4*)(qp + 8 * u);
    }
    __syncthreads();
    uint32_t qf[4][4];
    const __half2 s2 = __floats2half2_rn(0.125f, 0.125f);
#pragma unroll
    for (int ks = 0; ks < 4; ks++) {
        ldm4(qf[ks], aP + (uint32_t)(ks * 16 * 2));
#pragma unroll
        for (int r = 0; r < 4; r++) {
            __half2 v = *reinterpret_cast<__half2*>(&qf[ks][r]);
            v = __hmul2(v, s2);
            qf[ks][r] = h2u(v);
        }
    }
    __syncthreads();   // done with Q staging; Ps is now the P buffer

    float m0r = -INFINITY, m1r = -INFINITY, l0 = 0.f, l1 = 0.f;
    float oacc[8][4];
#pragma unroll
    for (int j = 0; j < 8; j++)
#pragma unroll
        for (int r = 0; r < 4; r++) oacc[j][r] = 0.f;

    const int lr = tid >> 2;           // 0..63
    const int lc = (tid & 3) * 16;     // halves
    const __half* kp = g_k + base + lc;
    const __half* vp = g_v + base + lc;
    const int prow = warp * 16 + g;

    for (int t0 = 0; t0 < S_DIM; t0 += 64) {
#pragma unroll
        for (int u = 0; u < 2; u++) {
            *(uint4*)&Ks[lr * 72 + lc + 8 * u] =
                *(const uint4*)(kp + (size_t)(t0 + lr) * rs + 8 * u);
            *(uint4*)&Vs[lr * 72 + lc + 8 * u] =
                *(const uint4*)(vp + (size_t)(t0 + lr) * rs + 8 * u);
        }
        if (tid < 64) maskv[tid] = mask[(size_t)b * S_DIM + t0 + tid];
        __syncthreads();

        // ---- S = Q K^T ----
        float sacc[8][4];
#pragma unroll
        for (int j = 0; j < 8; j++)
#pragma unroll
            for (int r = 0; r < 4; r++) sacc[j][r] = 0.f;
#pragma unroll
        for (int ks = 0; ks < 4; ks++) {
#pragma unroll
            for (int ntp = 0; ntp < 4; ntp++) {
                uint32_t bf[4];
                ldm4(bf, bK + (uint32_t)((ntp * 16 * 72 + ks * 16) * 2));
                mma16(sacc[2 * ntp],     qf[ks], bf[0], bf[1]);
                mma16(sacc[2 * ntp + 1], qf[ks], bf[2], bf[3]);
            }
        }

        // ---- +mask, row max ----
        float tm0 = -INFINITY, tm1 = -INFINITY;
#pragma unroll
        for (int nt = 0; nt < 8; nt++) {
            const float mv0 = maskv[nt * 8 + 2 * t];
            const float mv1 = maskv[nt * 8 + 2 * t + 1];
            sacc[nt][0] += mv0; sacc[nt][1] += mv1;
            sacc[nt][2] += mv0; sacc[nt][3] += mv1;
            tm0 = fmaxf(tm0, fmaxf(sacc[nt][0], sacc[nt][1]));
            tm1 = fmaxf(tm1, fmaxf(sacc[nt][2], sacc[nt][3]));
        }
        tm0 = fmaxf(tm0, __shfl_xor_sync(0xffffffffu, tm0, 1));
        tm0 = fmaxf(tm0, __shfl_xor_sync(0xffffffffu, tm0, 2));
        tm1 = fmaxf(tm1, __shfl_xor_sync(0xffffffffu, tm1, 1));
        tm1 = fmaxf(tm1, __shfl_xor_sync(0xffffffffu, tm1, 2));

        const float mn0 = fmaxf(m0r, tm0), mn1 = fmaxf(m1r, tm1);
        const float al0 = __expf(m0r - mn0), al1 = __expf(m1r - mn1);
        m0r = mn0; m1r = mn1;

        // ---- P = exp(S - m) -> fp16 smem; row sums ----
        float ls0 = 0.f, ls1 = 0.f;
#pragma unroll
        for (int nt = 0; nt < 8; nt++) {
            float p0 = __expf(sacc[nt][0] - mn0);
            float p1 = __expf(sacc[nt][1] - mn0);
            float p2 = __expf(sacc[nt][2] - mn1);
            float p3 = __expf(sacc[nt][3] - mn1);
            ls0 += p0 + p1; ls1 += p2 + p3;
            *(__half2*)&Ps[prow * 72 + nt * 8 + 2 * t]       = __floats2half2_rn(p0, p1);
            *(__half2*)&Ps[(prow + 8) * 72 + nt * 8 + 2 * t] = __floats2half2_rn(p2, p3);
        }
        ls0 += __shfl_xor_sync(0xffffffffu, ls0, 1);
        ls0 += __shfl_xor_sync(0xffffffffu, ls0, 2);
        ls1 += __shfl_xor_sync(0xffffffffu, ls1, 1);
        ls1 += __shfl_xor_sync(0xffffffffu, ls1, 2);
        l0 = l0 * al0 + ls0;
        l1 = l1 * al1 + ls1;

#pragma unroll
        for (int nt = 0; nt < 8; nt++) {
            oacc[nt][0] *= al0; oacc[nt][1] *= al0;
            oacc[nt][2] *= al1; oacc[nt][3] *= al1;
        }

        __syncwarp();   // P tile rows are warp-private

        // ---- O += P V ----
#pragma unroll
        for (int ks = 0; ks < 4; ks++) {
            uint32_t af[4];
            ldm4(af, aP + (uint32_t)(ks * 16 * 2));
#pragma unroll
            for (int ntp = 0; ntp < 4; ntp++) {
                uint32_t bf[4];
                ldm4t(bf, bV + (uint32_t)((ks * 16 * 72 + ntp * 16) * 2));
                mma16(oacc[2 * ntp],     af, bf[0], bf[1]);
                mma16(oacc[2 * ntp + 1], af, bf[2], bf[3]);
            }
        }
        __syncthreads();   // before next tile overwrites Ks/Vs
    }

    // ---- epilogue ----
    const float inv0 = 1.f / l0, inv1 = 1.f / l1;
    float* op = out + (size_t)(s0 + warp * 16) * rs + base;
#pragma unroll
    for (int nt = 0; nt < 8; nt++) {
        *(float2*)(op + (size_t)g * rs + nt * 8 + 2 * t) =
            make_float2(oacc[nt][0] * inv0, oacc[nt][1] * inv0);
        *(float2*)(op + (size_t)(g + 8) * rs + nt * 8 + 2 * t) =
            make_float2(oacc[nt][2] * inv1, oacc[nt][3] * inv1);
    }
}

// ---------------------------------------------------------------------------
extern "C" void kernel_launch(void* const* d_in, const int* in_sizes, int n_in,
                              void* d_out, int out_size)
{
    const float* X    = (const float*)d_in[0];
    const float* mask = (const float*)d_in[1];
    const float* Wq   = (const float*)d_in[2];
    const float* bq   = (const float*)d_in[3];
    const float* Wk   = (const float*)d_in[4];
    const float* bk   = (const float*)d_in[5];
    const float* Wv   = (const float*)d_in[6];
    const float* bv   = (const float*)d_in[7];
    float* out = (float*)d_out;

    dim3 ggrid(H_DIM / 128, M_DIM / 128, 3);   // (8, 64, 3)
    qkv_fp16<<<ggrid, 256>>>(X, Wq, bq, Wk, bk, Wv, bv);

    dim3 agrid(S_DIM / 128, B_DIM * NHEAD);    // (16, 64)
    attn_fp16<<<agrid, 256>>>(mask, out);
}

// round 5
// speedup vs baseline: 4.9786x; 1.2220x over previous
#include <cuda_runtime.h>
#include <cuda_fp16.h>
#include <math.h>
#include <stdint.h>

#define S_DIM 2048
#define B_DIM 4
#define H_DIM 1024
#define NHEAD 16
#define DHEAD 64
#define M_DIM (S_DIM * B_DIM)   // 8192

// fp16 hi/lo split inputs (persistent scratch)
__device__ __half g_Xh[(size_t)M_DIM * H_DIM];
__device__ __half g_Xl[(size_t)M_DIM * H_DIM];
__device__ __half g_Wh[3][(size_t)H_DIM * H_DIM];
__device__ __half g_Wl[3][(size_t)H_DIM * H_DIM];
// Projected q,k,v in fp16: [M, H]
__device__ __half g_q[(size_t)M_DIM * H_DIM];
__device__ __half g_k[(size_t)M_DIM * H_DIM];
__device__ __half g_v[(size_t)M_DIM * H_DIM];

extern __shared__ __half dynsm[];

// ---------------------------------------------------------------------------
// helpers
// ---------------------------------------------------------------------------
__device__ __forceinline__ uint32_t sma(const void* p) {
    return (uint32_t)__cvta_generic_to_shared(p);
}
__device__ __forceinline__ void ldm4(uint32_t r[4], uint32_t a) {
    asm volatile("ldmatrix.sync.aligned.m8n8.x4.shared.b16 {%0,%1,%2,%3},[%4];"
                 : "=r"(r[0]), "=r"(r[1]), "=r"(r[2]), "=r"(r[3]) : "r"(a));
}
__device__ __forceinline__ void ldm4t(uint32_t r[4], uint32_t a) {
    asm volatile("ldmatrix.sync.aligned.m8n8.x4.trans.shared.b16 {%0,%1,%2,%3},[%4];"
                 : "=r"(r[0]), "=r"(r[1]), "=r"(r[2]), "=r"(r[3]) : "r"(a));
}
__device__ __forceinline__ void mma16(float c[4], const uint32_t a[4],
                                      uint32_t b0, uint32_t b1) {
    asm volatile("mma.sync.aligned.m16n8k16.row.col.f32.f16.f16.f32 "
                 "{%0,%1,%2,%3},{%4,%5,%6,%7},{%8,%9},{%0,%1,%2,%3};"
                 : "+f"(c[0]), "+f"(c[1]), "+f"(c[2]), "+f"(c[3])
                 : "r"(a[0]), "r"(a[1]), "r"(a[2]), "r"(a[3]), "r"(b0), "r"(b1));
}
__device__ __forceinline__ uint32_t h2u(__half2 h) {
    return *reinterpret_cast<uint32_t*>(&h);
}
__device__ __forceinline__ void cpa16(uint32_t dst, const void* src) {
    asm volatile("cp.async.cg.shared.global [%0], [%1], 16;" :: "r"(dst), "l"(src));
}
__device__ __forceinline__ void cpa4(uint32_t dst, const void* src) {
    asm volatile("cp.async.ca.shared.global [%0], [%1], 4;" :: "r"(dst), "l"(src));
}
__device__ __forceinline__ void cp_commit() {
    asm volatile("cp.async.commit_group;");
}
template <int N>
__device__ __forceinline__ void cp_wait() {
    asm volatile("cp.async.wait_group %0;" :: "n"(N));
}

// ---------------------------------------------------------------------------
// Split pre-pass: fp32 -> (hi fp16, lo fp16), vectorized by 4.
// ---------------------------------------------------------------------------
__global__ __launch_bounds__(256) void split_fp32(const float* __restrict__ src,
                                                  __half* __restrict__ dh,
                                                  __half* __restrict__ dl, int n4)
{
    int i = blockIdx.x * blockDim.x + threadIdx.x;
    if (i >= n4) return;
    float4 v = ((const float4*)src)[i];
    __half h0 = __float2half_rn(v.x), h1 = __float2half_rn(v.y);
    __half h2 = __float2half_rn(v.z), h3 = __float2half_rn(v.w);
    __half l0 = __float2half_rn(v.x - __half2float(h0));
    __half l1 = __float2half_rn(v.y - __half2float(h1));
    __half l2 = __float2half_rn(v.z - __half2float(h2));
    __half l3 = __float2half_rn(v.w - __half2float(h3));
    ((uint2*)dh)[i] = make_uint2(h2u(__halves2half2(h0, h1)), h2u(__halves2half2(h2, h3)));
    ((uint2*)dl)[i] = make_uint2(h2u(__halves2half2(l0, l1)), h2u(__halves2half2(l2, l3)));
}

// ---------------------------------------------------------------------------
// QKV GEMM from pre-split fp16 (3-pass: hh+hl+lh ~ fp32 exact).
// CTA 128x128, BK=32, 256 threads, 2-stage cp.async double buffer.
// Stage layout (halfs, stride 40): Xh[5120] Xl[5120] Wh[5120] Wl[5120].
// ---------------------------------------------------------------------------
#define Q_STRIDE 40
#define Q_BUF_H  (128 * Q_STRIDE)        // 5120 halfs
#define Q_BUF_B  (Q_BUF_H * 2)           // 10240 bytes
#define Q_STAGE_B (4 * Q_BUF_B)          // 40960 bytes

__global__ __launch_bounds__(256) void qkv_gemm_v2(
    const float* __restrict__ bq, const float* __restrict__ bk,
    const float* __restrict__ bv)
{
    const int which = blockIdx.z;
    const float* bias = (which == 0) ? bq : (which == 1) ? bk : bv;
    __half* out       = (which == 0) ? g_q : (which == 1) ? g_k : g_v;
    const __half* Xh = g_Xh;
    const __half* Xl = g_Xl;
    const __half* Wh = g_Wh[which];
    const __half* Wl = g_Wl[which];

    const int tid  = threadIdx.x;
    const int lane = tid & 31, warp = tid >> 5;
    const int g = lane >> 2, t = lane & 3;
    const int wm = warp & 3, wn = warp >> 2;
    const int m0 = blockIdx.y * 128, n0 = blockIdx.x * 128;

    const uint32_t SB = sma(dynsm);

    // ldmatrix lane offsets (bytes, relative to buffer base)
    const int asel = lane & 15, ablk = (lane >> 4) * 8;
    const int br = lane & 7, bs = lane >> 3;
    const uint32_t aA_off = (uint32_t)(((wm * 32 + asel) * Q_STRIDE + ablk) * 2);
    const uint32_t bB_off =
        (uint32_t)(((wn * 64 + br + (bs >> 1) * 8) * Q_STRIDE + (bs & 1) * 8) * 2);

    // cp.async chunk coords (2 chunks per thread per matrix)
    int prow[2], pcol[2];
#pragma unroll
    for (int j = 0; j < 2; j++) {
        int c = tid + j * 256;
        prow[j] = c >> 2;
        pcol[j] = (c & 3) * 8;
    }

    auto prefetch = [&](int stage, int k0) {
        const uint32_t st = SB + stage * Q_STAGE_B;
#pragma unroll
        for (int j = 0; j < 2; j++) {
            const uint32_t doff = (uint32_t)((prow[j] * Q_STRIDE + pcol[j]) * 2);
            cpa16(st + doff,
                  Xh + (size_t)(m0 + prow[j]) * H_DIM + k0 + pcol[j]);
            cpa16(st + Q_BUF_B + doff,
                  Xl + (size_t)(m0 + prow[j]) * H_DIM + k0 + pcol[j]);
            cpa16(st + 2 * Q_BUF_B + doff,
                  Wh + (size_t)(n0 + prow[j]) * H_DIM + k0 + pcol[j]);
            cpa16(st + 3 * Q_BUF_B + doff,
                  Wl + (size_t)(n0 + prow[j]) * H_DIM + k0 + pcol[j]);
        }
        cp_commit();
    };

    float acc[2][8][4];
#pragma unroll
    for (int i = 0; i < 2; i++)
#pragma unroll
        for (int j = 0; j < 8; j++)
#pragma unroll
            for (int r = 0; r < 4; r++) acc[i][j][r] = 0.f;

    prefetch(0, 0);
    prefetch(1, 32);

    const int NT = H_DIM / 32;   // 32 k-tiles
#pragma unroll 1
    for (int kt = 0; kt < NT; kt++) {
        if (kt < NT - 1) cp_wait<1>(); else cp_wait<0>();
        __syncthreads();

        const int p = kt & 1;
        const uint32_t st  = SB + p * Q_STAGE_B;
        const uint32_t aXh = st + aA_off;
        const uint32_t aXl = st + Q_BUF_B + aA_off;
        const uint32_t bWh = st + 2 * Q_BUF_B + bB_off;
        const uint32_t bWl = st + 3 * Q_BUF_B + bB_off;

#pragma unroll
        for (int kc = 0; kc < 2; kc++) {
            uint32_t ah[2][4], al[2][4];
#pragma unroll
            for (int mt = 0; mt < 2; mt++) {
                ldm4(ah[mt], aXh + (uint32_t)((mt * 16 * Q_STRIDE + kc * 16) * 2));
                ldm4(al[mt], aXl + (uint32_t)((mt * 16 * Q_STRIDE + kc * 16) * 2));
            }
#pragma unroll
            for (int ntp = 0; ntp < 4; ntp++) {
                uint32_t bh[4], bl[4];
                ldm4(bh, bWh + (uint32_t)((ntp * 16 * Q_STRIDE + kc * 16) * 2));
                ldm4(bl, bWl + (uint32_t)((ntp * 16 * Q_STRIDE + kc * 16) * 2));
#pragma unroll
                for (int hn = 0; hn < 2; hn++) {
                    const int nt = 2 * ntp + hn;
                    const uint32_t b0h = bh[2 * hn], b1h = bh[2 * hn + 1];
                    const uint32_t b0l = bl[2 * hn], b1l = bl[2 * hn + 1];
#pragma unroll
                    for (int mt = 0; mt < 2; mt++) {
                        mma16(acc[mt][nt], ah[mt], b0h, b1h);
                        mma16(acc[mt][nt], ah[mt], b0l, b1l);
                        mma16(acc[mt][nt], al[mt], b0h, b1h);
                    }
                }
            }
        }
        __syncthreads();
        if (kt + 2 < NT) prefetch(p, (kt + 2) * 32);
    }

    // epilogue: +bias, convert to fp16
#pragma unroll
    for (int nt = 0; nt < 8; nt++) {
        const int col = n0 + wn * 64 + nt * 8 + 2 * t;
        const float b0 = bias[col], b1 = bias[col + 1];
#pragma unroll
        for (int mt = 0; mt < 2; mt++) {
            const int r0 = m0 + wm * 32 + mt * 16 + g;
            *(__half2*)(out + (size_t)r0 * H_DIM + col) =
                __floats2half2_rn(acc[mt][nt][0] + b0, acc[mt][nt][1] + b1);
            *(__half2*)(out + (size_t)(r0 + 8) * H_DIM + col) =
                __floats2half2_rn(acc[mt][nt][2] + b0, acc[mt][nt][3] + b1);
        }
    }
}

// ---------------------------------------------------------------------------
// Flash attention, fp16 mma + ldmatrix + 2-stage cp.async K/V pipeline.
// CTA = (head, 128 queries), 8 warps x 16 query rows, key tiles of 64.
// smem (halfs, stride 72): [stage][Ks 4608 | Vs 4608] x2, Ps 9216, mask 2x64 f32.
// ---------------------------------------------------------------------------
#define A_STRIDE 72
#define A_KV_H   (64 * A_STRIDE)         // 4608 halfs
#define A_STAGE_H (2 * A_KV_H)           // 9216 halfs (K+V)
#define A_PS_H   (128 * A_STRIDE)        // 9216 halfs
#define A_MASK_H (2 * A_STAGE_H + A_PS_H)  // half-offset of mask region (27648)

__global__ __launch_bounds__(256, 2) void attn_fp16_v2(const float* __restrict__ mask,
                                                       float* __restrict__ out)
{
    __half* Ps    = dynsm + 2 * A_STAGE_H;
    float*  maskv = (float*)(dynsm + A_MASK_H);   // [2][64]

    const int tid  = threadIdx.x;
    const int lane = tid & 31, warp = tid >> 5;
    const int g = lane >> 2, t = lane & 3;
    const int head = blockIdx.y, b = head >> 4, h = head & 15;
    const int s0 = blockIdx.x * 128;

    const size_t rs   = (size_t)B_DIM * H_DIM;          // 4096
    const size_t base = (size_t)b * H_DIM + h * DHEAD;

    const uint32_t SB = sma(dynsm);

    // ldmatrix lane offsets
    const int asel = lane & 15, ablk = (lane >> 4) * 8;
    const int br = lane & 7, bs = lane >> 3;
    const uint32_t aP = sma(Ps) + (uint32_t)(((warp * 16 + asel) * A_STRIDE + ablk) * 2);
    const uint32_t bK_off =
        (uint32_t)(((br + (bs >> 1) * 8) * A_STRIDE + (bs & 1) * 8) * 2);
    const uint32_t bV_off =
        (uint32_t)(((br + (bs & 1) * 8) * A_STRIDE + (bs >> 1) * 8) * 2);

    // cp.async chunk coords for K/V (2 chunks per thread per tensor)
    int prow[2], pcol[2];
#pragma unroll
    for (int j = 0; j < 2; j++) {
        int c = tid + j * 256;
        prow[j] = c >> 3;
        pcol[j] = (c & 7) * 8;
    }
    const __half* kg = g_k + base;
    const __half* vg = g_v + base;
    const float*  mg = mask + (size_t)b * S_DIM;

    auto prefetch = [&](int stage, int t0) {
        const uint32_t st = SB + (uint32_t)(stage * A_STAGE_H * 2);
#pragma unroll
        for (int j = 0; j < 2; j++) {
            const uint32_t doff = (uint32_t)((prow[j] * A_STRIDE + pcol[j]) * 2);
            cpa16(st + doff,               kg + (size_t)(t0 + prow[j]) * rs + pcol[j]);
            cpa16(st + A_KV_H * 2 + doff,  vg + (size_t)(t0 + prow[j]) * rs + pcol[j]);
        }
        if (tid < 64)
            cpa4(SB + (uint32_t)(A_MASK_H * 2 + (stage * 64 + tid) * 4), mg + t0 + tid);
        cp_commit();
    };

    prefetch(0, 0);
    prefetch(1, 64);

    // ---- stage Q into Ps, build Q fragments (scaled by 1/8, exact) ----
    {
        const int qlr = tid >> 1, qlc = (tid & 1) * 32;
        const __half* qp = g_q + base + (size_t)(s0 + qlr) * rs + qlc;
#pragma unroll
        for (int u = 0; u < 4; u++)
            *(uint4*)&Ps[qlr * A_STRIDE + qlc + 8 * u] = *(const uint4*)(qp + 8 * u);
    }
    __syncthreads();
    uint32_t qf[4][4];
    const __half2 s2 = __floats2half2_rn(0.125f, 0.125f);
#pragma unroll
    for (int ks = 0; ks < 4; ks++) {
        ldm4(qf[ks], aP + (uint32_t)(ks * 16 * 2));
#pragma unroll
        for (int r = 0; r < 4; r++) {
            __half2 v = *reinterpret_cast<__half2*>(&qf[ks][r]);
            v = __hmul2(v, s2);
            qf[ks][r] = h2u(v);
        }
    }
    __syncthreads();   // Q staging done; Ps becomes the P buffer

    float m0r = -INFINITY, m1r = -INFINITY, l0 = 0.f, l1 = 0.f;
    float oacc[8][4];
#pragma unroll
    for (int j = 0; j < 8; j++)
#pragma unroll
        for (int r = 0; r < 4; r++) oacc[j][r] = 0.f;

    const int prow_p = warp * 16 + g;
    const int NT = S_DIM / 64;   // 32

#pragma unroll 1
    for (int it = 0; it < NT; it++) {
        if (it < NT - 1) cp_wait<1>(); else cp_wait<0>();
        __syncthreads();

        const int p = it & 1;
        const uint32_t st = SB + (uint32_t)(p * A_STAGE_H * 2);
        const uint32_t bK = st + bK_off;
        const uint32_t bV = st + A_KV_H * 2 + bV_off;
        const float* mvp = maskv + p * 64;

        // ---- S = Q K^T ----
        float sacc[8][4];
#pragma unroll
        for (int j = 0; j < 8; j++)
#pragma unroll
            for (int r = 0; r < 4; r++) sacc[j][r] = 0.f;
#pragma unroll
        for (int ks = 0; ks < 4; ks++) {
#pragma unroll
            for (int ntp = 0; ntp < 4; ntp++) {
                uint32_t bf[4];
                ldm4(bf, bK + (uint32_t)((ntp * 16 * A_STRIDE + ks * 16) * 2));
                mma16(sacc[2 * ntp],     qf[ks], bf[0], bf[1]);
                mma16(sacc[2 * ntp + 1], qf[ks], bf[2], bf[3]);
            }
        }

        // ---- +mask, row max ----
        float tm0 = -INFINITY, tm1 = -INFINITY;
#pragma unroll
        for (int nt = 0; nt < 8; nt++) {
            const float mv0 = mvp[nt * 8 + 2 * t];
            const float mv1 = mvp[nt * 8 + 2 * t + 1];
            sacc[nt][0] += mv0; sacc[nt][1] += mv1;
            sacc[nt][2] += mv0; sacc[nt][3] += mv1;
            tm0 = fmaxf(tm0, fmaxf(sacc[nt][0], sacc[nt][1]));
            tm1 = fmaxf(tm1, fmaxf(sacc[nt][2], sacc[nt][3]));
        }
        tm0 = fmaxf(tm0, __shfl_xor_sync(0xffffffffu, tm0, 1));
        tm0 = fmaxf(tm0, __shfl_xor_sync(0xffffffffu, tm0, 2));
        tm1 = fmaxf(tm1, __shfl_xor_sync(0xffffffffu, tm1, 1));
        tm1 = fmaxf(tm1, __shfl_xor_sync(0xffffffffu, tm1, 2));

        const float mn0 = fmaxf(m0r, tm0), mn1 = fmaxf(m1r, tm1);
        const float al0 = __expf(m0r - mn0), al1 = __expf(m1r - mn1);
        m0r = mn0; m1r = mn1;

        // ---- P = exp(S - m) -> fp16 smem; row sums ----
        float ls0 = 0.f, ls1 = 0.f;
#pragma unroll
        for (int nt = 0; nt < 8; nt++) {
            float p0 = __expf(sacc[nt][0] - mn0);
            float p1 = __expf(sacc[nt][1] - mn0);
            float p2 = __expf(sacc[nt][2] - mn1);
            float p3 = __expf(sacc[nt][3] - mn1);
            ls0 += p0 + p1; ls1 += p2 + p3;
            *(__half2*)&Ps[prow_p * A_STRIDE + nt * 8 + 2 * t] =
                __floats2half2_rn(p0, p1);
            *(__half2*)&Ps[(prow_p + 8) * A_STRIDE + nt * 8 + 2 * t] =
                __floats2half2_rn(p2, p3);
        }
        ls0 += __shfl_xor_sync(0xffffffffu, ls0, 1);
        ls0 += __shfl_xor_sync(0xffffffffu, ls0, 2);
        ls1 += __shfl_xor_sync(0xffffffffu, ls1, 1);
        ls1 += __shfl_xor_sync(0xffffffffu, ls1, 2);
        l0 = l0 * al0 + ls0;
        l1 = l1 * al1 + ls1;

#pragma unroll
        for (int nt = 0; nt < 8; nt++) {
            oacc[nt][0] *= al0; oacc[nt][1] *= al0;
            oacc[nt][2] *= al1; oacc[nt][3] *= al1;
        }

        __syncwarp();   // P tile rows are warp-private

        // ---- O += P V ----
#pragma unroll
        for (int ks = 0; ks < 4; ks++) {
            uint32_t af[4];
            ldm4(af, aP + (uint32_t)(ks * 16 * 2));
#pragma unroll
            for (int ntp = 0; ntp < 4; ntp++) {
                uint32_t bf[4];
                ldm4t(bf, bV + (uint32_t)((ks * 16 * A_STRIDE + ntp * 16) * 2));
                mma16(oacc[2 * ntp],     af, bf[0], bf[1]);
                mma16(oacc[2 * ntp + 1], af, bf[2], bf[3]);
            }
        }
        __syncthreads();                 // all warps done with stage p
        if (it + 2 < NT) prefetch(p, (it + 2) * 64);
    }

    // ---- epilogue ----
    const float inv0 = 1.f / l0, inv1 = 1.f / l1;
    float* op = out + (size_t)(s0 + warp * 16) * rs + base;
#pragma unroll
    for (int nt = 0; nt < 8; nt++) {
        *(float2*)(op + (size_t)g * rs + nt * 8 + 2 * t) =
            make_float2(oacc[nt][0] * inv0, oacc[nt][1] * inv0);
        *(float2*)(op + (size_t)(g + 8) * rs + nt * 8 + 2 * t) =
            make_float2(oacc[nt][2] * inv1, oacc[nt][3] * inv1);
    }
}

// ---------------------------------------------------------------------------
extern "C" void kernel_launch(void* const* d_in, const int* in_sizes, int n_in,
                              void* d_out, int out_size)
{
    const float* X    = (const float*)d_in[0];
    const float* mask = (const float*)d_in[1];
    const float* Wq   = (const float*)d_in[2];
    const float* bq   = (const float*)d_in[3];
    const float* Wk   = (const float*)d_in[4];
    const float* bk   = (const float*)d_in[5];
    const float* Wv   = (const float*)d_in[6];
    const float* bv   = (const float*)d_in[7];
    float* out = (float*)d_out;

    // resolve device-global scratch addresses
    __half *Xh, *Xl, *Wh, *Wl;
    cudaGetSymbolAddress((void**)&Xh, g_Xh);
    cudaGetSymbolAddress((void**)&Xl, g_Xl);
    cudaGetSymbolAddress((void**)&Wh, g_Wh);
    cudaGetSymbolAddress((void**)&Wl, g_Wl);

    const size_t WSZ = (size_t)H_DIM * H_DIM;

    // split pre-pass
    const int nx4 = (int)((size_t)M_DIM * H_DIM / 4);
    const int nw4 = (int)(WSZ / 4);
    split_fp32<<<(nx4 + 255) / 256, 256>>>(X, Xh, Xl, nx4);
    split_fp32<<<(nw4 + 255) / 256, 256>>>(Wq, Wh + 0 * WSZ, Wl + 0 * WSZ, nw4);
    split_fp32<<<(nw4 + 255) / 256, 256>>>(Wk, Wh + 1 * WSZ, Wl + 1 * WSZ, nw4);
    split_fp32<<<(nw4 + 255) / 256, 256>>>(Wv, Wh + 2 * WSZ, Wl + 2 * WSZ, nw4);

    // QKV GEMM
    const int q_smem = 2 * Q_STAGE_B;   // 81920
    cudaFuncSetAttribute(qkv_gemm_v2, cudaFuncAttributeMaxDynamicSharedMemorySize,
                         q_smem);
    dim3 ggrid(H_DIM / 128, M_DIM / 128, 3);   // (8, 64, 3)
    qkv_gemm_v2<<<ggrid, 256, q_smem>>>(bq, bk, bv);

    // attention
    const int a_smem = (A_MASK_H * 2) + 2 * 64 * (int)sizeof(float);  // 55808
    cudaFuncSetAttribute(attn_fp16_v2, cudaFuncAttributeMaxDynamicSharedMemorySize,
                         a_smem);
    dim3 agrid(S_DIM / 128, B_DIM * NHEAD);    // (16, 64)
    attn_fp16_v2<<<agrid, 256, a_smem>>>(mask, out);
}

// round 6
// speedup vs baseline: 7.6507x; 1.5367x over previous
#include <cuda_runtime.h>
#include <cuda_fp16.h>
#include <math.h>
#include <stdint.h>

#define S_DIM 2048
#define B_DIM 4
#define H_DIM 1024
#define NHEAD 16
#define DHEAD 64
#define M_DIM (S_DIM * B_DIM)   // 8192

// fp16 inputs (persistent scratch)
__device__ __half g_Xh[(size_t)M_DIM * H_DIM];
__device__ __half g_Wh[3][(size_t)H_DIM * H_DIM];
// Projected q,k,v in fp16: [M, H]
__device__ __half g_q[(size_t)M_DIM * H_DIM];
__device__ __half g_k[(size_t)M_DIM * H_DIM];
__device__ __half g_v[(size_t)M_DIM * H_DIM];

extern __shared__ __half dynsm[];

// ---------------------------------------------------------------------------
// helpers
// ---------------------------------------------------------------------------
__device__ __forceinline__ uint32_t sma(const void* p) {
    return (uint32_t)__cvta_generic_to_shared(p);
}
__device__ __forceinline__ void ldm4(uint32_t r[4], uint32_t a) {
    asm volatile("ldmatrix.sync.aligned.m8n8.x4.shared.b16 {%0,%1,%2,%3},[%4];"
                 : "=r"(r[0]), "=r"(r[1]), "=r"(r[2]), "=r"(r[3]) : "r"(a));
}
__device__ __forceinline__ void ldm4t(uint32_t r[4], uint32_t a) {
    asm volatile("ldmatrix.sync.aligned.m8n8.x4.trans.shared.b16 {%0,%1,%2,%3},[%4];"
                 : "=r"(r[0]), "=r"(r[1]), "=r"(r[2]), "=r"(r[3]) : "r"(a));
}
__device__ __forceinline__ void mma16(float c[4], const uint32_t a[4],
                                      uint32_t b0, uint32_t b1) {
    asm volatile("mma.sync.aligned.m16n8k16.row.col.f32.f16.f16.f32 "
                 "{%0,%1,%2,%3},{%4,%5,%6,%7},{%8,%9},{%0,%1,%2,%3};"
                 : "+f"(c[0]), "+f"(c[1]), "+f"(c[2]), "+f"(c[3])
                 : "r"(a[0]), "r"(a[1]), "r"(a[2]), "r"(a[3]), "r"(b0), "r"(b1));
}
__device__ __forceinline__ uint32_t h2u(__half2 h) {
    return *reinterpret_cast<uint32_t*>(&h);
}
__device__ __forceinline__ void cpa16(uint32_t dst, const void* src) {
    asm volatile("cp.async.cg.shared.global [%0], [%1], 16;" :: "r"(dst), "l"(src));
}
__device__ __forceinline__ void cpa4(uint32_t dst, const void* src) {
    asm volatile("cp.async.ca.shared.global [%0], [%1], 4;" :: "r"(dst), "l"(src));
}
__device__ __forceinline__ void cp_commit() {
    asm volatile("cp.async.commit_group;");
}
template <int N>
__device__ __forceinline__ void cp_wait() {
    asm volatile("cp.async.wait_group %0;" :: "n"(N));
}

// ---------------------------------------------------------------------------
// Convert pre-pass: fp32 -> fp16, vectorized by 4.
// ---------------------------------------------------------------------------
__global__ __launch_bounds__(256) void to_half(const float* __restrict__ src,
                                               __half* __restrict__ dst, int n4)
{
    int i = blockIdx.x * blockDim.x + threadIdx.x;
    if (i >= n4) return;
    float4 v = ((const float4*)src)[i];
    ((uint2*)dst)[i] = make_uint2(
        h2u(__floats2half2_rn(v.x, v.y)), h2u(__floats2half2_rn(v.z, v.w)));
}

// ---------------------------------------------------------------------------
// Single-pass fp16 QKV GEMM. out[m][n] = sum_k X[m][k]*W[n][k] + bias[n].
// CTA 128x128, BK=32, 256 threads, 3-stage cp.async pipeline.
// Stage layout (halfs, stride 40): Xh[5120] | Wh[5120].
// ---------------------------------------------------------------------------
#define Q_STRIDE 40
#define Q_BUF_H  (128 * Q_STRIDE)        // 5120 halfs
#define Q_BUF_B  (Q_BUF_H * 2)           // 10240 bytes
#define Q_STAGE_B (2 * Q_BUF_B)          // 20480 bytes
#define Q_NSTAGE 3

__global__ __launch_bounds__(256) void qkv_gemm_v3(
    const float* __restrict__ bq, const float* __restrict__ bk,
    const float* __restrict__ bv)
{
    const int which = blockIdx.z;
    const float* bias = (which == 0) ? bq : (which == 1) ? bk : bv;
    __half* out       = (which == 0) ? g_q : (which == 1) ? g_k : g_v;
    const __half* Xh = g_Xh;
    const __half* Wh = g_Wh[which];

    const int tid  = threadIdx.x;
    const int lane = tid & 31, warp = tid >> 5;
    const int g = lane >> 2, t = lane & 3;
    const int wm = warp & 3, wn = warp >> 2;
    const int m0 = blockIdx.y * 128, n0 = blockIdx.x * 128;

    const uint32_t SB = sma(dynsm);

    // ldmatrix lane offsets (bytes, relative to stage base)
    const int asel = lane & 15, ablk = (lane >> 4) * 8;
    const int br = lane & 7, bs = lane >> 3;
    const uint32_t aA_off = (uint32_t)(((wm * 32 + asel) * Q_STRIDE + ablk) * 2);
    const uint32_t bB_off = (uint32_t)(Q_BUF_B +
        ((wn * 64 + br + (bs >> 1) * 8) * Q_STRIDE + (bs & 1) * 8) * 2);

    // cp.async chunk coords (2 chunks per thread per matrix)
    int prow[2], pcol[2];
#pragma unroll
    for (int j = 0; j < 2; j++) {
        int c = tid + j * 256;
        prow[j] = c >> 2;
        pcol[j] = (c & 3) * 8;
    }

    auto prefetch = [&](int stage, int k0) {
        const uint32_t st = SB + stage * Q_STAGE_B;
#pragma unroll
        for (int j = 0; j < 2; j++) {
            const uint32_t doff = (uint32_t)((prow[j] * Q_STRIDE + pcol[j]) * 2);
            cpa16(st + doff,
                  Xh + (size_t)(m0 + prow[j]) * H_DIM + k0 + pcol[j]);
            cpa16(st + Q_BUF_B + doff,
                  Wh + (size_t)(n0 + prow[j]) * H_DIM + k0 + pcol[j]);
        }
        cp_commit();
    };

    float acc[2][8][4];
#pragma unroll
    for (int i = 0; i < 2; i++)
#pragma unroll
        for (int j = 0; j < 8; j++)
#pragma unroll
            for (int r = 0; r < 4; r++) acc[i][j][r] = 0.f;

    prefetch(0, 0);
    prefetch(1, 32);
    prefetch(2, 64);

    const int NT = H_DIM / 32;   // 32 k-tiles
#pragma unroll 1
    for (int kt = 0; kt < NT; kt++) {
        cp_wait<Q_NSTAGE - 1>();   // group kt complete (one group/iter invariant)
        __syncthreads();

        const int p = kt % Q_NSTAGE;
        const uint32_t st  = SB + p * Q_STAGE_B;
        const uint32_t aXp = st + aA_off;
        const uint32_t bWp = st + bB_off;

#pragma unroll
        for (int kc = 0; kc < 2; kc++) {
            uint32_t ah[2][4];
#pragma unroll
            for (int mt = 0; mt < 2; mt++)
                ldm4(ah[mt], aXp + (uint32_t)((mt * 16 * Q_STRIDE + kc * 16) * 2));
#pragma unroll
            for (int ntp = 0; ntp < 4; ntp++) {
                uint32_t bh[4];
                ldm4(bh, bWp + (uint32_t)((ntp * 16 * Q_STRIDE + kc * 16) * 2));
#pragma unroll
                for (int hn = 0; hn < 2; hn++) {
                    const int nt = 2 * ntp + hn;
#pragma unroll
                    for (int mt = 0; mt < 2; mt++)
                        mma16(acc[mt][nt], ah[mt], bh[2 * hn], bh[2 * hn + 1]);
                }
            }
        }
        __syncthreads();
        if (kt + Q_NSTAGE < NT) prefetch(p, (kt + Q_NSTAGE) * 32);
        else                    cp_commit();   // empty group keeps wait invariant
    }

    // epilogue: +bias, convert to fp16
#pragma unroll
    for (int nt = 0; nt < 8; nt++) {
        const int col = n0 + wn * 64 + nt * 8 + 2 * t;
        const float b0 = bias[col], b1 = bias[col + 1];
#pragma unroll
        for (int mt = 0; mt < 2; mt++) {
            const int r0 = m0 + wm * 32 + mt * 16 + g;
            *(__half2*)(out + (size_t)r0 * H_DIM + col) =
                __floats2half2_rn(acc[mt][nt][0] + b0, acc[mt][nt][1] + b1);
            *(__half2*)(out + (size_t)(r0 + 8) * H_DIM + col) =
                __floats2half2_rn(acc[mt][nt][2] + b0, acc[mt][nt][3] + b1);
        }
    }
}

// ---------------------------------------------------------------------------
// Flash attention, fp16 mma + ldmatrix + 2-stage cp.async K/V pipeline.
// (unchanged from R5)
// ---------------------------------------------------------------------------
#define A_STRIDE 72
#define A_KV_H   (64 * A_STRIDE)           // 4608 halfs
#define A_STAGE_H (2 * A_KV_H)             // 9216 halfs (K+V)
#define A_PS_H   (128 * A_STRIDE)          // 9216 halfs
#define A_MASK_H (2 * A_STAGE_H + A_PS_H)  // half-offset of mask region

__global__ __launch_bounds__(256, 2) void attn_fp16_v2(const float* __restrict__ mask,
                                                       float* __restrict__ out)
{
    __half* Ps    = dynsm + 2 * A_STAGE_H;
    float*  maskv = (float*)(dynsm + A_MASK_H);   // [2][64]

    const int tid  = threadIdx.x;
    const int lane = tid & 31, warp = tid >> 5;
    const int g = lane >> 2, t = lane & 3;
    const int head = blockIdx.y, b = head >> 4, h = head & 15;
    const int s0 = blockIdx.x * 128;

    const size_t rs   = (size_t)B_DIM * H_DIM;          // 4096
    const size_t base = (size_t)b * H_DIM + h * DHEAD;

    const uint32_t SB = sma(dynsm);

    const int asel = lane & 15, ablk = (lane >> 4) * 8;
    const int br = lane & 7, bs = lane >> 3;
    const uint32_t aP = sma(Ps) + (uint32_t)(((warp * 16 + asel) * A_STRIDE + ablk) * 2);
    const uint32_t bK_off =
        (uint32_t)(((br + (bs >> 1) * 8) * A_STRIDE + (bs & 1) * 8) * 2);
    const uint32_t bV_off =
        (uint32_t)(((br + (bs & 1) * 8) * A_STRIDE + (bs >> 1) * 8) * 2);

    int prow[2], pcol[2];
#pragma unroll
    for (int j = 0; j < 2; j++) {
        int c = tid + j * 256;
        prow[j] = c >> 3;
        pcol[j] = (c & 7) * 8;
    }
    const __half* kg = g_k + base;
    const __half* vg = g_v + base;
    const float*  mg = mask + (size_t)b * S_DIM;

    auto prefetch = [&](int stage, int t0) {
        const uint32_t st = SB + (uint32_t)(stage * A_STAGE_H * 2);
#pragma unroll
        for (int j = 0; j < 2; j++) {
            const uint32_t doff = (uint32_t)((prow[j] * A_STRIDE + pcol[j]) * 2);
            cpa16(st + doff,               kg + (size_t)(t0 + prow[j]) * rs + pcol[j]);
            cpa16(st + A_KV_H * 2 + doff,  vg + (size_t)(t0 + prow[j]) * rs + pcol[j]);
        }
        if (tid < 64)
            cpa4(SB + (uint32_t)(A_MASK_H * 2 + (stage * 64 + tid) * 4), mg + t0 + tid);
        cp_commit();
    };

    prefetch(0, 0);
    prefetch(1, 64);

    // ---- stage Q into Ps, build Q fragments (scaled by 1/8, exact) ----
    {
        const int qlr = tid >> 1, qlc = (tid & 1) * 32;
        const __half* qp = g_q + base + (size_t)(s0 + qlr) * rs + qlc;
#pragma unroll
        for (int u = 0; u < 4; u++)
            *(uint4*)&Ps[qlr * A_STRIDE + qlc + 8 * u] = *(const uint4*)(qp + 8 * u);
    }
    __syncthreads();
    uint32_t qf[4][4];
    const __half2 s2 = __floats2half2_rn(0.125f, 0.125f);
#pragma unroll
    for (int ks = 0; ks < 4; ks++) {
        ldm4(qf[ks], aP + (uint32_t)(ks * 16 * 2));
#pragma unroll
        for (int r = 0; r < 4; r++) {
            __half2 v = *reinterpret_cast<__half2*>(&qf[ks][r]);
            v = __hmul2(v, s2);
            qf[ks][r] = h2u(v);
        }
    }
    __syncthreads();   // Q staging done; Ps becomes the P buffer

    float m0r = -INFINITY, m1r = -INFINITY, l0 = 0.f, l1 = 0.f;
    float oacc[8][4];
#pragma unroll
    for (int j = 0; j < 8; j++)
#pragma unroll
        for (int r = 0; r < 4; r++) oacc[j][r] = 0.f;

    const int prow_p = warp * 16 + g;
    const int NT = S_DIM / 64;   // 32

#pragma unroll 1
    for (int it = 0; it < NT; it++) {
        if (it < NT - 1) cp_wait<1>(); else cp_wait<0>();
        __syncthreads();

        const int p = it & 1;
        const uint32_t st = SB + (uint32_t)(p * A_STAGE_H * 2);
        const uint32_t bK = st + bK_off;
        const uint32_t bV = st + A_KV_H * 2 + bV_off;
        const float* mvp = maskv + p * 64;

        // ---- S = Q K^T ----
        float sacc[8][4];
#pragma unroll
        for (int j = 0; j < 8; j++)
#pragma unroll
            for (int r = 0; r < 4; r++) sacc[j][r] = 0.f;
#pragma unroll
        for (int ks = 0; ks < 4; ks++) {
#pragma unroll
            for (int ntp = 0; ntp < 4; ntp++) {
                uint32_t bf[4];
                ldm4(bf, bK + (uint32_t)((ntp * 16 * A_STRIDE + ks * 16) * 2));
                mma16(sacc[2 * ntp],     qf[ks], bf[0], bf[1]);
                mma16(sacc[2 * ntp + 1], qf[ks], bf[2], bf[3]);
            }
        }

        // ---- +mask, row max ----
        float tm0 = -INFINITY, tm1 = -INFINITY;
#pragma unroll
        for (int nt = 0; nt < 8; nt++) {
            const float mv0 = mvp[nt * 8 + 2 * t];
            const float mv1 = mvp[nt * 8 + 2 * t + 1];
            sacc[nt][0] += mv0; sacc[nt][1] += mv1;
            sacc[nt][2] += mv0; sacc[nt][3] += mv1;
            tm0 = fmaxf(tm0, fmaxf(sacc[nt][0], sacc[nt][1]));
            tm1 = fmaxf(tm1, fmaxf(sacc[nt][2], sacc[nt][3]));
        }
        tm0 = fmaxf(tm0, __shfl_xor_sync(0xffffffffu, tm0, 1));
        tm0 = fmaxf(tm0, __shfl_xor_sync(0xffffffffu, tm0, 2));
        tm1 = fmaxf(tm1, __shfl_xor_sync(0xffffffffu, tm1, 1));
        tm1 = fmaxf(tm1, __shfl_xor_sync(0xffffffffu, tm1, 2));

        const float mn0 = fmaxf(m0r, tm0), mn1 = fmaxf(m1r, tm1);
        const float al0 = __expf(m0r - mn0), al1 = __expf(m1r - mn1);
        m0r = mn0; m1r = mn1;

        // ---- P = exp(S - m) -> fp16 smem; row sums ----
        float ls0 = 0.f, ls1 = 0.f;
#pragma unroll
        for (int nt = 0; nt < 8; nt++) {
            float p0 = __expf(sacc[nt][0] - mn0);
            float p1 = __expf(sacc[nt][1] - mn0);
            float p2 = __expf(sacc[nt][2] - mn1);
            float p3 = __expf(sacc[nt][3] - mn1);
            ls0 += p0 + p1; ls1 += p2 + p3;
            *(__half2*)&Ps[prow_p * A_STRIDE + nt * 8 + 2 * t] =
                __floats2half2_rn(p0, p1);
            *(__half2*)&Ps[(prow_p + 8) * A_STRIDE + nt * 8 + 2 * t] =
                __floats2half2_rn(p2, p3);
        }
        ls0 += __shfl_xor_sync(0xffffffffu, ls0, 1);
        ls0 += __shfl_xor_sync(0xffffffffu, ls0, 2);
        ls1 += __shfl_xor_sync(0xffffffffu, ls1, 1);
        ls1 += __shfl_xor_sync(0xffffffffu, ls1, 2);
        l0 = l0 * al0 + ls0;
        l1 = l1 * al1 + ls1;

#pragma unroll
        for (int nt = 0; nt < 8; nt++) {
            oacc[nt][0] *= al0; oacc[nt][1] *= al0;
            oacc[nt][2] *= al1; oacc[nt][3] *= al1;
        }

        __syncwarp();   // P tile rows are warp-private

        // ---- O += P V ----
#pragma unroll
        for (int ks = 0; ks < 4; ks++) {
            uint32_t af[4];
            ldm4(af, aP + (uint32_t)(ks * 16 * 2));
#pragma unroll
            for (int ntp = 0; ntp < 4; ntp++) {
                uint32_t bf[4];
                ldm4t(bf, bV + (uint32_t)((ks * 16 * A_STRIDE + ntp * 16) * 2));
                mma16(oacc[2 * ntp],     af, bf[0], bf[1]);
                mma16(oacc[2 * ntp + 1], af, bf[2], bf[3]);
            }
        }
        __syncthreads();                 // all warps done with stage p
        if (it + 2 < NT) prefetch(p, (it + 2) * 64);
    }

    // ---- epilogue ----
    const float inv0 = 1.f / l0, inv1 = 1.f / l1;
    float* op = out + (size_t)(s0 + warp * 16) * rs + base;
#pragma unroll
    for (int nt = 0; nt < 8; nt++) {
        *(float2*)(op + (size_t)g * rs + nt * 8 + 2 * t) =
            make_float2(oacc[nt][0] * inv0, oacc[nt][1] * inv0);
        *(float2*)(op + (size_t)(g + 8) * rs + nt * 8 + 2 * t) =
            make_float2(oacc[nt][2] * inv1, oacc[nt][3] * inv1);
    }
}

// ---------------------------------------------------------------------------
extern "C" void kernel_launch(void* const* d_in, const int* in_sizes, int n_in,
                              void* d_out, int out_size)
{
    const float* X    = (const float*)d_in[0];
    const float* mask = (const float*)d_in[1];
    const float* Wq   = (const float*)d_in[2];
    const float* bq   = (const float*)d_in[3];
    const float* Wk   = (const float*)d_in[4];
    const float* bk   = (const float*)d_in[5];
    const float* Wv   = (const float*)d_in[6];
    const float* bv   = (const float*)d_in[7];
    float* out = (float*)d_out;

    __half *Xh, *Wh;
    cudaGetSymbolAddress((void**)&Xh, g_Xh);
    cudaGetSymbolAddress((void**)&Wh, g_Wh);

    const size_t WSZ = (size_t)H_DIM * H_DIM;

    // convert pre-pass
    const int nx4 = (int)((size_t)M_DIM * H_DIM / 4);
    const int nw4 = (int)(WSZ / 4);
    to_half<<<(nx4 + 255) / 256, 256>>>(X, Xh, nx4);
    to_half<<<(nw4 + 255) / 256, 256>>>(Wq, Wh + 0 * WSZ, nw4);
    to_half<<<(nw4 + 255) / 256, 256>>>(Wk, Wh + 1 * WSZ, nw4);
    to_half<<<(nw4 + 255) / 256, 256>>>(Wv, Wh + 2 * WSZ, nw4);

    // QKV GEMM (single-pass fp16, 3-stage pipeline)
    const int q_smem = Q_NSTAGE * Q_STAGE_B;   // 61440
    cudaFuncSetAttribute(qkv_gemm_v3, cudaFuncAttributeMaxDynamicSharedMemorySize,
                         q_smem);
    dim3 ggrid(H_DIM / 128, M_DIM / 128, 3);   // (8, 64, 3)
    qkv_gemm_v3<<<ggrid, 256, q_smem>>>(bq, bk, bv);

    // attention (unchanged)
    const int a_smem = (A_MASK_H * 2) + 2 * 64 * (int)sizeof(float);  // 55808
    cudaFuncSetAttribute(attn_fp16_v2, cudaFuncAttributeMaxDynamicSharedMemorySize,
                         a_smem);
    dim3 agrid(S_DIM / 128, B_DIM * NHEAD);    // (16, 64)
    attn_fp16_v2<<<agrid, 256, a_smem>>>(mask, out);
}

// round 7
// speedup vs baseline: 8.0986x; 1.0585x over previous
#include <cuda_runtime.h>
#include <cuda_fp16.h>
#include <math.h>
#include <stdint.h>

#define S_DIM 2048
#define B_DIM 4
#define H_DIM 1024
#define NHEAD 16
#define DHEAD 64
#define M_DIM (S_DIM * B_DIM)   // 8192

// fp16 inputs (persistent scratch)
__device__ __half g_Xh[(size_t)M_DIM * H_DIM];
__device__ __half g_Wh[3][(size_t)H_DIM * H_DIM];
// Projected q,k,v in fp16: [M, H]
__device__ __half g_q[(size_t)M_DIM * H_DIM];
__device__ __half g_k[(size_t)M_DIM * H_DIM];
__device__ __half g_v[(size_t)M_DIM * H_DIM];

extern __shared__ __half dynsm[];

// ---------------------------------------------------------------------------
// helpers
// ---------------------------------------------------------------------------
__device__ __forceinline__ uint32_t sma(const void* p) {
    return (uint32_t)__cvta_generic_to_shared(p);
}
__device__ __forceinline__ void ldm4(uint32_t r[4], uint32_t a) {
    asm volatile("ldmatrix.sync.aligned.m8n8.x4.shared.b16 {%0,%1,%2,%3},[%4];"
                 : "=r"(r[0]), "=r"(r[1]), "=r"(r[2]), "=r"(r[3]) : "r"(a));
}
__device__ __forceinline__ void ldm4t(uint32_t r[4], uint32_t a) {
    asm volatile("ldmatrix.sync.aligned.m8n8.x4.trans.shared.b16 {%0,%1,%2,%3},[%4];"
                 : "=r"(r[0]), "=r"(r[1]), "=r"(r[2]), "=r"(r[3]) : "r"(a));
}
__device__ __forceinline__ void mma16(float c[4], const uint32_t a[4],
                                      uint32_t b0, uint32_t b1) {
    asm volatile("mma.sync.aligned.m16n8k16.row.col.f32.f16.f16.f32 "
                 "{%0,%1,%2,%3},{%4,%5,%6,%7},{%8,%9},{%0,%1,%2,%3};"
                 : "+f"(c[0]), "+f"(c[1]), "+f"(c[2]), "+f"(c[3])
                 : "r"(a[0]), "r"(a[1]), "r"(a[2]), "r"(a[3]), "r"(b0), "r"(b1));
}
__device__ __forceinline__ uint32_t h2u(__half2 h) {
    return *reinterpret_cast<uint32_t*>(&h);
}
__device__ __forceinline__ void cpa16(uint32_t dst, const void* src) {
    asm volatile("cp.async.cg.shared.global [%0], [%1], 16;" :: "r"(dst), "l"(src));
}
__device__ __forceinline__ void cpa4(uint32_t dst, const void* src) {
    asm volatile("cp.async.ca.shared.global [%0], [%1], 4;" :: "r"(dst), "l"(src));
}
__device__ __forceinline__ void cp_commit() {
    asm volatile("cp.async.commit_group;");
}
template <int N>
__device__ __forceinline__ void cp_wait() {
    asm volatile("cp.async.wait_group %0;" :: "n"(N));
}

// ---------------------------------------------------------------------------
// Convert pre-pass: fp32 -> fp16, vectorized by 4.
// ---------------------------------------------------------------------------
__global__ __launch_bounds__(256) void to_half(const float* __restrict__ src,
                                               __half* __restrict__ dst, int n4)
{
    int i = blockIdx.x * blockDim.x + threadIdx.x;
    if (i >= n4) return;
    float4 v = ((const float4*)src)[i];
    ((uint2*)dst)[i] = make_uint2(
        h2u(__floats2half2_rn(v.x, v.y)), h2u(__floats2half2_rn(v.z, v.w)));
}

// ---------------------------------------------------------------------------
// Single-pass fp16 QKV GEMM (unchanged from R6).
// CTA 128x128, BK=32, 256 threads, 3-stage cp.async pipeline.
// ---------------------------------------------------------------------------
#define Q_STRIDE 40
#define Q_BUF_H  (128 * Q_STRIDE)        // 5120 halfs
#define Q_BUF_B  (Q_BUF_H * 2)           // 10240 bytes
#define Q_STAGE_B (2 * Q_BUF_B)          // 20480 bytes
#define Q_NSTAGE 3

__global__ __launch_bounds__(256) void qkv_gemm_v3(
    const float* __restrict__ bq, const float* __restrict__ bk,
    const float* __restrict__ bv)
{
    const int which = blockIdx.z;
    const float* bias = (which == 0) ? bq : (which == 1) ? bk : bv;
    __half* out       = (which == 0) ? g_q : (which == 1) ? g_k : g_v;
    const __half* Xh = g_Xh;
    const __half* Wh = g_Wh[which];

    const int tid  = threadIdx.x;
    const int lane = tid & 31, warp = tid >> 5;
    const int g = lane >> 2, t = lane & 3;
    const int wm = warp & 3, wn = warp >> 2;
    const int m0 = blockIdx.y * 128, n0 = blockIdx.x * 128;

    const uint32_t SB = sma(dynsm);

    const int asel = lane & 15, ablk = (lane >> 4) * 8;
    const int br = lane & 7, bs = lane >> 3;
    const uint32_t aA_off = (uint32_t)(((wm * 32 + asel) * Q_STRIDE + ablk) * 2);
    const uint32_t bB_off = (uint32_t)(Q_BUF_B +
        ((wn * 64 + br + (bs >> 1) * 8) * Q_STRIDE + (bs & 1) * 8) * 2);

    int prow[2], pcol[2];
#pragma unroll
    for (int j = 0; j < 2; j++) {
        int c = tid + j * 256;
        prow[j] = c >> 2;
        pcol[j] = (c & 3) * 8;
    }

    auto prefetch = [&](int stage, int k0) {
        const uint32_t st = SB + stage * Q_STAGE_B;
#pragma unroll
        for (int j = 0; j < 2; j++) {
            const uint32_t doff = (uint32_t)((prow[j] * Q_STRIDE + pcol[j]) * 2);
            cpa16(st + doff,
                  Xh + (size_t)(m0 + prow[j]) * H_DIM + k0 + pcol[j]);
            cpa16(st + Q_BUF_B + doff,
                  Wh + (size_t)(n0 + prow[j]) * H_DIM + k0 + pcol[j]);
        }
        cp_commit();
    };

    float acc[2][8][4];
#pragma unroll
    for (int i = 0; i < 2; i++)
#pragma unroll
        for (int j = 0; j < 8; j++)
#pragma unroll
            for (int r = 0; r < 4; r++) acc[i][j][r] = 0.f;

    prefetch(0, 0);
    prefetch(1, 32);
    prefetch(2, 64);

    const int NT = H_DIM / 32;   // 32 k-tiles
#pragma unroll 1
    for (int kt = 0; kt < NT; kt++) {
        cp_wait<Q_NSTAGE - 1>();
        __syncthreads();

        const int p = kt % Q_NSTAGE;
        const uint32_t st  = SB + p * Q_STAGE_B;
        const uint32_t aXp = st + aA_off;
        const uint32_t bWp = st + bB_off;

#pragma unroll
        for (int kc = 0; kc < 2; kc++) {
            uint32_t ah[2][4];
#pragma unroll
            for (int mt = 0; mt < 2; mt++)
                ldm4(ah[mt], aXp + (uint32_t)((mt * 16 * Q_STRIDE + kc * 16) * 2));
#pragma unroll
            for (int ntp = 0; ntp < 4; ntp++) {
                uint32_t bh[4];
                ldm4(bh, bWp + (uint32_t)((ntp * 16 * Q_STRIDE + kc * 16) * 2));
#pragma unroll
                for (int hn = 0; hn < 2; hn++) {
                    const int nt = 2 * ntp + hn;
#pragma unroll
                    for (int mt = 0; mt < 2; mt++)
                        mma16(acc[mt][nt], ah[mt], bh[2 * hn], bh[2 * hn + 1]);
                }
            }
        }
        __syncthreads();
        if (kt + Q_NSTAGE < NT) prefetch(p, (kt + Q_NSTAGE) * 32);
        else                    cp_commit();
    }

#pragma unroll
    for (int nt = 0; nt < 8; nt++) {
        const int col = n0 + wn * 64 + nt * 8 + 2 * t;
        const float b0 = bias[col], b1 = bias[col + 1];
#pragma unroll
        for (int mt = 0; mt < 2; mt++) {
            const int r0 = m0 + wm * 32 + mt * 16 + g;
            *(__half2*)(out + (size_t)r0 * H_DIM + col) =
                __floats2half2_rn(acc[mt][nt][0] + b0, acc[mt][nt][1] + b1);
            *(__half2*)(out + (size_t)(r0 + 8) * H_DIM + col) =
                __floats2half2_rn(acc[mt][nt][2] + b0, acc[mt][nt][3] + b1);
        }
    }
}

// ---------------------------------------------------------------------------
// Flash attention v3: fp16 mma, 2-stage cp.async K/V pipeline, P kept in
// registers (QK C-fragment layout == PV A-fragment layout; no smem round trip).
// smem: [stage][Ks 64x72 | Vs 64x72] x2  +  mask[2][64] f32  = 37376 B.
// ---------------------------------------------------------------------------
#define A_STRIDE 72
#define A_KV_H   (64 * A_STRIDE)           // 4608 halfs
#define A_STAGE_H (2 * A_KV_H)             // 9216 halfs (K+V)
#define A_MASK_H (2 * A_STAGE_H)           // half-offset of mask region

__global__ __launch_bounds__(256, 2) void attn_fp16_v3(const float* __restrict__ mask,
                                                       float* __restrict__ out)
{
    float* maskv = (float*)(dynsm + A_MASK_H);   // [2][64]

    const int tid  = threadIdx.x;
    const int lane = tid & 31, warp = tid >> 5;
    const int g = lane >> 2, t = lane & 3;
    const int head = blockIdx.y, b = head >> 4, h = head & 15;
    const int s0 = blockIdx.x * 128;

    const size_t rs   = (size_t)B_DIM * H_DIM;          // 4096
    const size_t base = (size_t)b * H_DIM + h * DHEAD;

    const uint32_t SB = sma(dynsm);

    const int asel = lane & 15, ablk = (lane >> 4) * 8;
    const int br = lane & 7, bs = lane >> 3;
    const uint32_t aQ = SB + (uint32_t)(((warp * 16 + asel) * A_STRIDE + ablk) * 2);
    const uint32_t bK_off =
        (uint32_t)(((br + (bs >> 1) * 8) * A_STRIDE + (bs & 1) * 8) * 2);
    const uint32_t bV_off =
        (uint32_t)(((br + (bs & 1) * 8) * A_STRIDE + (bs >> 1) * 8) * 2);

    int prow[2], pcol[2];
#pragma unroll
    for (int j = 0; j < 2; j++) {
        int c = tid + j * 256;
        prow[j] = c >> 3;
        pcol[j] = (c & 7) * 8;
    }
    const __half* kg = g_k + base;
    const __half* vg = g_v + base;
    const float*  mg = mask + (size_t)b * S_DIM;

    auto prefetch = [&](int stage, int t0) {
        const uint32_t st = SB + (uint32_t)(stage * A_STAGE_H * 2);
#pragma unroll
        for (int j = 0; j < 2; j++) {
            const uint32_t doff = (uint32_t)((prow[j] * A_STRIDE + pcol[j]) * 2);
            cpa16(st + doff,               kg + (size_t)(t0 + prow[j]) * rs + pcol[j]);
            cpa16(st + A_KV_H * 2 + doff,  vg + (size_t)(t0 + prow[j]) * rs + pcol[j]);
        }
        if (tid < 64)
            cpa4(SB + (uint32_t)(A_MASK_H * 2 + (stage * 64 + tid) * 4), mg + t0 + tid);
        cp_commit();
    };

    // ---- stage Q through stage-0 K/V region (prologue only) ----
    {
        const int qlr = tid >> 1, qlc = (tid & 1) * 32;
        const __half* qp = g_q + base + (size_t)(s0 + qlr) * rs + qlc;
#pragma unroll
        for (int u = 0; u < 4; u++)
            *(uint4*)&dynsm[qlr * A_STRIDE + qlc + 8 * u] = *(const uint4*)(qp + 8 * u);
    }
    __syncthreads();
    uint32_t qf[4][4];
    const __half2 s2 = __floats2half2_rn(0.125f, 0.125f);   // exact power of 2
#pragma unroll
    for (int ks = 0; ks < 4; ks++) {
        ldm4(qf[ks], aQ + (uint32_t)(ks * 16 * 2));
#pragma unroll
        for (int r = 0; r < 4; r++) {
            __half2 v = *reinterpret_cast<__half2*>(&qf[ks][r]);
            v = __hmul2(v, s2);
            qf[ks][r] = h2u(v);
        }
    }
    __syncthreads();   // Q consumed; stage-0 buffer free for the pipeline

    prefetch(0, 0);
    prefetch(1, 64);

    float m0r = -INFINITY, m1r = -INFINITY, l0 = 0.f, l1 = 0.f;
    float oacc[8][4];
#pragma unroll
    for (int j = 0; j < 8; j++)
#pragma unroll
        for (int r = 0; r < 4; r++) oacc[j][r] = 0.f;

    const int NT = S_DIM / 64;   // 32

#pragma unroll 1
    for (int it = 0; it < NT; it++) {
        if (it < NT - 1) cp_wait<1>(); else cp_wait<0>();
        __syncthreads();

        const int p = it & 1;
        const uint32_t st = SB + (uint32_t)(p * A_STAGE_H * 2);
        const uint32_t bK = st + bK_off;
        const uint32_t bV = st + A_KV_H * 2 + bV_off;
        const float* mvp = maskv + p * 64;

        // ---- S = Q K^T ----
        float sacc[8][4];
#pragma unroll
        for (int j = 0; j < 8; j++)
#pragma unroll
            for (int r = 0; r < 4; r++) sacc[j][r] = 0.f;
#pragma unroll
        for (int ks = 0; ks < 4; ks++) {
#pragma unroll
            for (int ntp = 0; ntp < 4; ntp++) {
                uint32_t bf[4];
                ldm4(bf, bK + (uint32_t)((ntp * 16 * A_STRIDE + ks * 16) * 2));
                mma16(sacc[2 * ntp],     qf[ks], bf[0], bf[1]);
                mma16(sacc[2 * ntp + 1], qf[ks], bf[2], bf[3]);
            }
        }

        // ---- +mask, row max ----
        float tm0 = -INFINITY, tm1 = -INFINITY;
#pragma unroll
        for (int nt = 0; nt < 8; nt++) {
            const float mv0 = mvp[nt * 8 + 2 * t];
            const float mv1 = mvp[nt * 8 + 2 * t + 1];
            sacc[nt][0] += mv0; sacc[nt][1] += mv1;
            sacc[nt][2] += mv0; sacc[nt][3] += mv1;
            tm0 = fmaxf(tm0, fmaxf(sacc[nt][0], sacc[nt][1]));
            tm1 = fmaxf(tm1, fmaxf(sacc[nt][2], sacc[nt][3]));
        }
        tm0 = fmaxf(tm0, __shfl_xor_sync(0xffffffffu, tm0, 1));
        tm0 = fmaxf(tm0, __shfl_xor_sync(0xffffffffu, tm0, 2));
        tm1 = fmaxf(tm1, __shfl_xor_sync(0xffffffffu, tm1, 1));
        tm1 = fmaxf(tm1, __shfl_xor_sync(0xffffffffu, tm1, 2));

        const float mn0 = fmaxf(m0r, tm0), mn1 = fmaxf(m1r, tm1);
        const float al0 = __expf(m0r - mn0), al1 = __expf(m1r - mn1);
        m0r = mn0; m1r = mn1;

        // ---- P = exp(S - m) in-place; row sums ----
        float ls0 = 0.f, ls1 = 0.f;
#pragma unroll
        for (int nt = 0; nt < 8; nt++) {
            sacc[nt][0] = __expf(sacc[nt][0] - mn0);
            sacc[nt][1] = __expf(sacc[nt][1] - mn0);
            sacc[nt][2] = __expf(sacc[nt][2] - mn1);
            sacc[nt][3] = __expf(sacc[nt][3] - mn1);
            ls0 += sacc[nt][0] + sacc[nt][1];
            ls1 += sacc[nt][2] + sacc[nt][3];
        }
        ls0 += __shfl_xor_sync(0xffffffffu, ls0, 1);
        ls0 += __shfl_xor_sync(0xffffffffu, ls0, 2);
        ls1 += __shfl_xor_sync(0xffffffffu, ls1, 1);
        ls1 += __shfl_xor_sync(0xffffffffu, ls1, 2);
        l0 = l0 * al0 + ls0;
        l1 = l1 * al1 + ls1;

        // ---- P -> half2 A-fragments, entirely in registers ----
        // For keys 16*ks..16*ks+15: a0=P[g][2t,2t+1]     = sacc[2ks][0..1]
        //                           a1=P[g+8][2t,2t+1]   = sacc[2ks][2..3]
        //                           a2=P[g][8+2t,8+2t+1] = sacc[2ks+1][0..1]
        //                           a3=P[g+8][...]       = sacc[2ks+1][2..3]
        uint32_t af[4][4];
#pragma unroll
        for (int ks = 0; ks < 4; ks++) {
            af[ks][0] = h2u(__floats2half2_rn(sacc[2 * ks][0],     sacc[2 * ks][1]));
            af[ks][1] = h2u(__floats2half2_rn(sacc[2 * ks][2],     sacc[2 * ks][3]));
            af[ks][2] = h2u(__floats2half2_rn(sacc[2 * ks + 1][0], sacc[2 * ks + 1][1]));
            af[ks][3] = h2u(__floats2half2_rn(sacc[2 * ks + 1][2], sacc[2 * ks + 1][3]));
        }

        // ---- rescale O ----
#pragma unroll
        for (int nt = 0; nt < 8; nt++) {
            oacc[nt][0] *= al0; oacc[nt][1] *= al0;
            oacc[nt][2] *= al1; oacc[nt][3] *= al1;
        }

        // ---- O += P V ----
#pragma unroll
        for (int ks = 0; ks < 4; ks++) {
#pragma unroll
            for (int ntp = 0; ntp < 4; ntp++) {
                uint32_t bf[4];
                ldm4t(bf, bV + (uint32_t)((ks * 16 * A_STRIDE + ntp * 16) * 2));
                mma16(oacc[2 * ntp],     af[ks], bf[0], bf[1]);
                mma16(oacc[2 * ntp + 1], af[ks], bf[2], bf[3]);
            }
        }
        __syncthreads();                 // all warps done with stage p
        if (it + 2 < NT) prefetch(p, (it + 2) * 64);
    }

    // ---- epilogue ----
    const float inv0 = 1.f / l0, inv1 = 1.f / l1;
    float* op = out + (size_t)(s0 + warp * 16) * rs + base;
#pragma unroll
    for (int nt = 0; nt < 8; nt++) {
        *(float2*)(op + (size_t)g * rs + nt * 8 + 2 * t) =
            make_float2(oacc[nt][0] * inv0, oacc[nt][1] * inv0);
        *(float2*)(op + (size_t)(g + 8) * rs + nt * 8 + 2 * t) =
            make_float2(oacc[nt][2] * inv1, oacc[nt][3] * inv1);
    }
}

// ---------------------------------------------------------------------------
extern "C" void kernel_launch(void* const* d_in, const int* in_sizes, int n_in,
                              void* d_out, int out_size)
{
    const float* X    = (const float*)d_in[0];
    const float* mask = (const float*)d_in[1];
    const float* Wq   = (const float*)d_in[2];
    const float* bq   = (const float*)d_in[3];
    const float* Wk   = (const float*)d_in[4];
    const float* bk   = (const float*)d_in[5];
    const float* Wv   = (const float*)d_in[6];
    const float* bv   = (const float*)d_in[7];
    float* out = (float*)d_out;

    __half *Xh, *Wh;
    cudaGetSymbolAddress((void**)&Xh, g_Xh);
    cudaGetSymbolAddress((void**)&Wh, g_Wh);

    const size_t WSZ = (size_t)H_DIM * H_DIM;

    // convert pre-pass
    const int nx4 = (int)((size_t)M_DIM * H_DIM / 4);
    const int nw4 = (int)(WSZ / 4);
    to_half<<<(nx4 + 255) / 256, 256>>>(X, Xh, nx4);
    to_half<<<(nw4 + 255) / 256, 256>>>(Wq, Wh + 0 * WSZ, nw4);
    to_half<<<(nw4 + 255) / 256, 256>>>(Wk, Wh + 1 * WSZ, nw4);
    to_half<<<(nw4 + 255) / 256, 256>>>(Wv, Wh + 2 * WSZ, nw4);

    // QKV GEMM (single-pass fp16, 3-stage pipeline)
    const int q_smem = Q_NSTAGE * Q_STAGE_B;   // 61440
    cudaFuncSetAttribute(qkv_gemm_v3, cudaFuncAttributeMaxDynamicSharedMemorySize,
                         q_smem);
    dim3 ggrid(H_DIM / 128, M_DIM / 128, 3);   // (8, 64, 3)
    qkv_gemm_v3<<<ggrid, 256, q_smem>>>(bq, bk, bv);

    // attention (register-P)
    const int a_smem = (A_MASK_H * 2) + 2 * 64 * (int)sizeof(float);  // 37376
    cudaFuncSetAttribute(attn_fp16_v3, cudaFuncAttributeMaxDynamicSharedMemorySize,
                         a_smem);
    dim3 agrid(S_DIM / 128, B_DIM * NHEAD);    // (16, 64)
    attn_fp16_v3<<<agrid, 256, a_smem>>>(mask, out);
}